// round 11
// baseline (speedup 1.0000x reference)
#include <cuda_runtime.h>
#include <cuda_fp16.h>
#include <math.h>
#include <stdint.h>

// ---------------- problem constants ----------------
#define B_ 256
#define S_ 14
#define C_ 2513
#define SB 3584          // S_*B_
#define BH 262144        // B_*H_
#define G4 4096          // 4*H_
#define NSM 152

// ---------------- fp16 mma GEMM config (128x128, 256 thr, occ 2) ----------
#define STAGE_H   4096
#define SLOT_H    (2 * STAGE_H)
#define NSTAGE    4
#define MAIN_H    (NSTAGE * SLOT_H)          // 32768 halves = 65536 B
#define SMEM_LSTM ((MAIN_H + 128 * 32) * 2)  // 73728 B (also used by DAG)
#define SMEM_LIN  (MAIN_H * 2 + 512)         // 66048 B

// DAG work decomposition
#define NSTEP 15
#define UNROLL_TILES 7616            // sum_j 64*nact_j
#define CLS_NB 20                    // ceil(2513/128)
#define CLS_TILES (CLS_NB * 28)      // 560
#define TOT_TILES (UNROLL_TILES + CLS_TILES)

// ---------------- scratch (device globals) ----------------
__device__ __half g_xT [SB * 1024];
__device__ float  g_xg_r[(size_t)SB * G4];
__device__ float  g_xg_u[(size_t)SB * G4];
__device__ float  g_hs [SB * 1024];
__device__ float  g_cs [SB * 1024];
__device__ __half g_hu [2 * SB * 1024];
__device__ float  g_cu [SB * 1024];
__device__ __half g_hn [SB * 1024];
__device__ __half g_wihr[(size_t)G4 * 1024];
__device__ __half g_wihu[(size_t)G4 * 1024];
__device__ __half g_whhu[(size_t)G4 * 1024];
__device__ __half g_wc [(size_t)2560 * 1024];
__device__ int    g_work;
__device__ int    g_cnt[NSTEP * 28];
__device__ int    g_nopsink;

__device__ __forceinline__ float sigf(float x) { return 1.0f / (1.0f + expf(-x)); }

// logical-k permutation within each 32-k block
__device__ __forceinline__ int perm_l(int p) {
    int b = (p >> 2) & 1, t = p >> 3, j = p & 3;
    return b * 16 + ((j < 2) ? (2 * t + j) : (2 * t + 8 + (j - 2)));
}
__device__ __forceinline__ int inv_l(int l) {
    int b = l >> 4, r = l & 15, hi = r >> 3, t = (r >> 1) & 3, e = r & 1;
    return t * 8 + b * 4 + hi * 2 + e;
}

// ---------------- low-level helpers ----------------
__device__ __forceinline__ uint32_t smaddr(const void* p) {
    uint32_t a;
    asm("{ .reg .u64 t; cvta.to.shared.u64 t, %1; cvt.u32.u64 %0, t; }" : "=r"(a) : "l"(p));
    return a;
}
__device__ __forceinline__ void cp16(uint32_t d, const void* s) {
    asm volatile("cp.async.cg.shared.global [%0], [%1], 16;" :: "r"(d), "l"(s));
}
__device__ __forceinline__ void cp16z(uint32_t d, const void* s, int sz) {
    asm volatile("cp.async.cg.shared.global [%0], [%1], 16, %2;" :: "r"(d), "l"(s), "r"(sz));
}
__device__ __forceinline__ void cpcommit() { asm volatile("cp.async.commit_group;"); }
template <int N>
__device__ __forceinline__ void cpwait() { asm volatile("cp.async.wait_group %0;" :: "n"(N)); }
__device__ __forceinline__ int ld_acq(const int* p) {
    int v; asm volatile("ld.acquire.gpu.global.b32 %0, [%1];" : "=r"(v) : "l"(p)); return v;
}
__device__ __forceinline__ void red_rel(int* p) {
    asm volatile("red.release.gpu.global.add.s32 [%0], 1;" :: "l"(p));
}
__device__ __forceinline__ void mma16(float* d, const uint32_t* a, const uint32_t* b) {
    asm volatile(
        "mma.sync.aligned.m16n8k16.row.col.f32.f16.f16.f32 "
        "{%0,%1,%2,%3},{%4,%5,%6,%7},{%8,%9},{%0,%1,%2,%3};"
        : "+f"(d[0]), "+f"(d[1]), "+f"(d[2]), "+f"(d[3])
        : "r"(a[0]), "r"(a[1]), "r"(a[2]), "r"(a[3]), "r"(b[0]), "r"(b[1]));
}

// ---------------- stage issue (256 threads, 128x32 A + 128x32 B) ----------
template <int EDGE>
__device__ __forceinline__ void stage_issue(
    __half* sm, int slot, const __half* __restrict__ A, const __half* __restrict__ W,
    int m0, int n0, int kt, int Nb, int tid)
{
    __half* dA = sm + slot * SLOT_H;
    __half* dB = dA + STAGE_H;
    const __half* Ap = A + (size_t)m0 * 1024 + kt * 32;
    const __half* Wp = W + (size_t)n0 * 1024 + kt * 32;
#pragma unroll
    for (int i = 0; i < 2; i++) {
        int c = tid + (i << 8);
        int row = c >> 2, c16 = c & 3;
        cp16(smaddr(dA + row * 32 + c16 * 8), Ap + (size_t)row * 1024 + c16 * 8);
        if (EDGE) {
            int ok = (n0 + row < Nb);
            cp16z(smaddr(dB + row * 32 + c16 * 8),
                  Wp + (size_t)(ok ? row : 0) * 1024 + c16 * 8, ok ? 16 : 0);
        } else {
            cp16(smaddr(dB + row * 32 + c16 * 8), Wp + (size_t)row * 1024 + c16 * 8);
        }
    }
    cpcommit();
}

// ---------------- stage compute: 64x32 warp tile, 32 MMAs ------------------
__device__ __forceinline__ void stage_compute(
    const __half* sm, int slot, int wm, int wn, int g, int tig, float acc[4][4][4])
{
    const __half* bA = sm + slot * SLOT_H + (size_t)(wm * 64 + g) * 32 + tig * 8;
    const __half* bB = sm + slot * SLOT_H + STAGE_H + (size_t)(wn * 32 + g) * 32 + tig * 8;
    uint4 bq[4];
#pragma unroll
    for (int ni = 0; ni < 4; ni++)
        bq[ni] = *(const uint4*)(bB + ni * 8 * 32);
#pragma unroll
    for (int mp = 0; mp < 2; mp++) {
        const int m0i = mp * 2, m1i = mp * 2 + 1;
        uint4 alo0 = *(const uint4*)(bA + m0i * 16 * 32);
        uint4 ahi0 = *(const uint4*)(bA + (m0i * 16 + 8) * 32);
        uint4 alo1 = *(const uint4*)(bA + m1i * 16 * 32);
        uint4 ahi1 = *(const uint4*)(bA + (m1i * 16 + 8) * 32);
        uint32_t a00[4] = {alo0.x, ahi0.x, alo0.y, ahi0.y};
        uint32_t a01[4] = {alo0.z, ahi0.z, alo0.w, ahi0.w};
        uint32_t a10[4] = {alo1.x, ahi1.x, alo1.y, ahi1.y};
        uint32_t a11[4] = {alo1.z, ahi1.z, alo1.w, ahi1.w};
#pragma unroll
        for (int ni = 0; ni < 4; ni++) {
            uint32_t bf0[2] = {bq[ni].x, bq[ni].y};
            mma16(acc[m0i][ni], a00, bf0);
        }
#pragma unroll
        for (int ni = 0; ni < 4; ni++) {
            uint32_t bf0[2] = {bq[ni].x, bq[ni].y};
            mma16(acc[m1i][ni], a10, bf0);
        }
#pragma unroll
        for (int ni = 0; ni < 4; ni++) {
            uint32_t bf1[2] = {bq[ni].z, bq[ni].w};
            mma16(acc[m0i][ni], a01, bf1);
        }
#pragma unroll
        for (int ni = 0; ni < 4; ni++) {
            uint32_t bf1[2] = {bq[ni].z, bq[ni].w};
            mma16(acc[m1i][ni], a11, bf1);
        }
    }
}

// ---------------- full K=1024 mainloop (4-stage, 1 sync/iter) --------------
template <int EDGE>
__device__ __forceinline__ void run_mainloop(
    __half* sm, const __half* __restrict__ A, const __half* __restrict__ W,
    int m0, int n0, int Nb, float acc[4][4][4],
    int tid, int wm, int wn, int g, int tig)
{
    stage_issue<EDGE>(sm, 0, A, W, m0, n0, 0, Nb, tid);
    stage_issue<EDGE>(sm, 1, A, W, m0, n0, 1, Nb, tid);
    stage_issue<EDGE>(sm, 2, A, W, m0, n0, 2, Nb, tid);
#pragma unroll 1
    for (int kt = 0; kt < 32; kt++) {
        int slot = kt & 3;
        if (kt < 30)       cpwait<2>();
        else if (kt == 30) cpwait<1>();
        else               cpwait<0>();
        __syncthreads();
        if (kt + 3 < 32) stage_issue<EDGE>(sm, (kt + 3) & 3, A, W, m0, n0, kt + 3, Nb, tid);
        stage_compute(sm, slot, wm, wn, g, tig, acc);
    }
}

// ---------------- persistent DAG kernel: unroll steps + classifier ---------
__global__ void __launch_bounds__(256, 2) k_dag(
    __half* __restrict__ hu0, __half* __restrict__ hu1,
    const __half* __restrict__ Whh, const float* __restrict__ xg,
    float* __restrict__ cu, __half* __restrict__ hn,
    const __half* __restrict__ wc, const float* __restrict__ bc,
    float* __restrict__ out)
{
    extern __shared__ __half sm[];
    __half* hsm  = sm + MAIN_H;                 // 8KB scratch (h tile / bias)
    __shared__ int s_wid;
    const int tid = threadIdx.x, lane = tid & 31, wid = tid >> 5;
    const int wm = wid & 1, wn = wid >> 1, g = lane >> 2, tig = lane & 3;

#pragma unroll 1
    while (true) {
        __syncthreads();
        if (tid == 0) s_wid = atomicAdd(&g_work, 1);
        __syncthreads();
        int w = s_wid;
        if (w >= TOT_TILES) break;

        float acc[4][4][4];
#pragma unroll
        for (int a = 0; a < 4; a++)
#pragma unroll
            for (int b = 0; b < 4; b++)
#pragma unroll
                for (int c = 0; c < 4; c++) acc[a][b][c] = 0.f;

        if (w < UNROLL_TILES) {
            // ---- unroll LSTM tile ----
            int j = 0, r = w;
#pragma unroll 1
            for (; j < NSTEP; j++) {
                int na = (15 - j < 14) ? (15 - j) : 14;
                int sz = na << 6;               // 64*nact tiles per step
                if (r < sz) break;
                r -= sz;
            }
            int mb = r >> 5, nb = r & 31;
            int m0 = mb * 128, n0 = nb * 128;

            if (j > 0) {
                if (tid == 0) {
                    const int* cp = &g_cnt[(j - 1) * 28 + mb];
                    while (ld_acq(cp) < 32) __nanosleep(64);
                }
                __syncthreads();
            }
            const __half* Hin = (j & 1) ? hu1 : hu0;
            __half*       Ho  = (j & 1) ? hu0 : hu1;
            const int final_t = 14 - j;

            run_mainloop<0>(sm, Hin, Whh, m0, n0, 0x7fffffff, acc, tid, wm, wn, g, tig);

#pragma unroll
            for (int mi = 0; mi < 4; mi++) {
                const int R0 = m0 + wm * 64 + mi * 16;
#pragma unroll
                for (int ni = 0; ni < 4; ni++) {
                    const int V0 = n0 + wn * 32 + ni * 8;
                    float c0 = acc[mi][ni][0], c1 = acc[mi][ni][1];
                    float c2 = acc[mi][ni][2], c3 = acc[mi][ni][3];
                    int p = tig & 1;
                    float x = p ? c0 : c2, y = p ? c1 : c3;
                    float sx = __shfl_xor_sync(0xffffffffu, x, 1);
                    float sy = __shfl_xor_sync(0xffffffffu, y, 1);
                    float pi, pf, pg, po; int row;
                    if (!p) { pi = c0; pf = c1; pg = sx; po = sy; row = R0 + g; }
                    else    { pi = sx; pf = sy; pg = c2; po = c3; row = R0 + g + 8; }
                    int u = (V0 >> 2) + (tig >> 1);
                    float4 xv = *(const float4*)(xg + (size_t)row * G4 + u * 4);
                    float ci = __ldcg(&cu[(size_t)row * 1024 + u]);
                    float cn = sigf(pf + xv.y) * ci + sigf(pi + xv.x) * tanhf(pg + xv.z);
                    float hv = sigf(po + xv.w) * tanhf(cn);
                    asm volatile("st.global.cg.f32 [%0], %1;"
                                 :: "l"(&cu[(size_t)row * 1024 + u]), "f"(cn));
                    int ul = u - (n0 >> 2);
                    hsm[(row - m0) * 32 + inv_l(ul)] = __float2half_rn(hv);
                }
            }
            __syncthreads();
            {
                int r2 = tid >> 1, seg = tid & 1;
                int m = m0 + r2;
                const uint4* src = (const uint4*)(hsm + r2 * 32 + seg * 16);
                uint4 a = src[0], b = src[1];
                __half* gd = Ho + (size_t)m * 1024 + (n0 >> 2) + seg * 16;
                ((uint4*)gd)[0] = a; ((uint4*)gd)[1] = b;
                if ((m >> 8) == final_t) {
                    __half* fd = hn + (size_t)m * 1024 + (n0 >> 2) + seg * 16;
                    ((uint4*)fd)[0] = a; ((uint4*)fd)[1] = b;
                }
            }
            __threadfence();
            __syncthreads();
            if (tid == 0) red_rel(&g_cnt[j * 28 + mb]);
        } else {
            // ---- classifier tile ----
            int r = w - UNROLL_TILES;
            int mb = r / CLS_NB, nb = r % CLS_NB;
            int m0 = mb * 128, n0 = nb * 128;
            int t = mb >> 1, jd = 14 - t;
            if (tid == 0) {
                const int* c0p = &g_cnt[jd * 28 + 2 * t];
                const int* c1p = &g_cnt[jd * 28 + 2 * t + 1];
                while (ld_acq(c0p) < 32) __nanosleep(64);
                while (ld_acq(c1p) < 32) __nanosleep(64);
            }
            __syncthreads();

            float* biasS = (float*)hsm;
            if (tid < 128) {
                int np = n0 + tid;
                biasS[tid] = (np < C_) ? bc[np] : 0.f;
            }
            run_mainloop<1>(sm, hn, wc, m0, n0, C_, acc, tid, wm, wn, g, tig);

#pragma unroll
            for (int mi = 0; mi < 4; mi++) {
                const int R0 = m0 + wm * 64 + mi * 16;
#pragma unroll
                for (int ni = 0; ni < 4; ni++) {
                    const int v = n0 + wn * 32 + ni * 8 + 2 * tig;
                    const float bA0 = biasS[v - n0], bA1 = biasS[v - n0 + 1];
                    const int r1 = R0 + g, r2 = R0 + g + 8;
                    int or1 = (r1 & 255) * S_ + (r1 >> 8);
                    int or2 = (r2 & 255) * S_ + (r2 >> 8);
                    if (v < C_) {
                        out[(size_t)or1 * C_ + v] = acc[mi][ni][0] + bA0;
                        out[(size_t)or2 * C_ + v] = acc[mi][ni][2] + bA0;
                    }
                    if (v + 1 < C_) {
                        out[(size_t)or1 * C_ + v + 1] = acc[mi][ni][1] + bA1;
                        out[(size_t)or2 * C_ + v + 1] = acc[mi][ni][3] + bA1;
                    }
                }
            }
        }
    }
}

// ---------------- tensor-core linear (projection) --------------------------
__global__ void __launch_bounds__(256, 2) k_mma_proj(
    const __half* __restrict__ A, const __half* __restrict__ W,
    float* __restrict__ Out, const float* __restrict__ b0,
    const float* __restrict__ b1)
{
    extern __shared__ __half sm[];
    float* biasS = (float*)(sm + MAIN_H);
    const int tid = threadIdx.x, lane = tid & 31, wid = tid >> 5;
    const int wm = wid & 1, wn = wid >> 1, g = lane >> 2, tig = lane & 3;
    const int m0 = blockIdx.y * 128, n0 = blockIdx.x * 128;

    if (tid < 128) {
        int np = n0 + tid;
        int wr = ((np & 3) << 10) | (np >> 2);
        biasS[tid] = b0[wr] + b1[wr];
    }

    float acc[4][4][4];
#pragma unroll
    for (int a = 0; a < 4; a++)
#pragma unroll
        for (int b = 0; b < 4; b++)
#pragma unroll
            for (int c = 0; c < 4; c++) acc[a][b][c] = 0.f;

    run_mainloop<0>(sm, A, W, m0, n0, 0x7fffffff, acc, tid, wm, wn, g, tig);

#pragma unroll
    for (int mi = 0; mi < 4; mi++) {
        const int R0 = m0 + wm * 64 + mi * 16;
#pragma unroll
        for (int ni = 0; ni < 4; ni++) {
            const int v = n0 + wn * 32 + ni * 8 + 2 * tig;
            const float bA0 = biasS[v - n0], bA1 = biasS[v - n0 + 1];
            const int r1 = R0 + g, r2 = R0 + g + 8;
            float2 s1 = make_float2(acc[mi][ni][0] + bA0, acc[mi][ni][1] + bA1);
            float2 s2 = make_float2(acc[mi][ni][2] + bA0, acc[mi][ni][3] + bA1);
            *(float2*)(Out + (size_t)r1 * G4 + v) = s1;
            *(float2*)(Out + (size_t)r2 * G4 + v) = s2;
        }
    }
}

// ---------------- merged prep kernel (fp32 -> fp16 + k-permute) ------------
#define PREP_XT   (SB * 32)
#define PREP_W    (G4 * 32)
#define PREP_WC   (C_ * 32)
#define PREP_TOT  (PREP_XT + 3 * PREP_W + PREP_WC)

__global__ void k_prep_all(
    const float* __restrict__ inp,
    const float* __restrict__ Wih_r, const float* __restrict__ Wih_u,
    const float* __restrict__ Whh_u, const float* __restrict__ Wc,
    __half* __restrict__ xT, __half* __restrict__ wihr, __half* __restrict__ wihu,
    __half* __restrict__ whhu, __half* __restrict__ wc)
{
    int idx = blockIdx.x * blockDim.x + threadIdx.x;
    if (idx >= PREP_TOT) return;
    const float* src;
    __half* dstbase;
    int r, b32;
    if (idx < PREP_XT) {
        r = idx >> 5; b32 = idx & 31;
        int b = r % B_, s = r / B_;
        src = inp + (size_t)(b * S_ + s) * 1024 + b32 * 32;
        dstbase = xT;
    } else {
        int t = idx - PREP_XT;
        int seg = t / PREP_W;
        if (seg < 3) {
            int u = t - seg * PREP_W;
            r = u >> 5; b32 = u & 31;
            int wr = ((r & 3) << 10) | (r >> 2);
            const float* W = (seg == 0) ? Wih_r : (seg == 1) ? Wih_u : Whh_u;
            src = W + (size_t)wr * 1024 + b32 * 32;
            dstbase = (seg == 0) ? wihr : (seg == 1) ? wihu : whhu;
        } else {
            int u = t - 3 * PREP_W;
            r = u >> 5; b32 = u & 31;
            src = Wc + (size_t)r * 1024 + b32 * 32;
            dstbase = wc;
        }
    }
    float v[32];
#pragma unroll
    for (int i = 0; i < 8; i++) *(float4*)&v[i * 4] = *(const float4*)(src + i * 4);
    __half h[32];
#pragma unroll
    for (int p = 0; p < 32; p++) h[p] = __float2half_rn(v[perm_l(p)]);
    uint4* dst = (uint4*)(dstbase + (size_t)r * 1024 + b32 * 32);
#pragma unroll
    for (int i = 0; i < 4; i++) dst[i] = ((const uint4*)h)[i];
}

__global__ void k_nop() {
    if (threadIdx.x == 0 && blockIdx.x == 12345) g_nopsink = 1;
}

// h (fp32 logical) -> fp16 permuted
__global__ void k_h2h(const float* __restrict__ in, __half* __restrict__ out) {
    int idx = blockIdx.x * blockDim.x + threadIdx.x;
    if (idx >= SB * 32) return;
    int r = idx >> 5, b32 = idx & 31;
    const float* src = in + (size_t)r * 1024 + b32 * 32;
    float v[32];
#pragma unroll
    for (int i = 0; i < 8; i++) *(float4*)&v[i * 4] = *(const float4*)(src + i * 4);
    __half h[32];
#pragma unroll
    for (int p = 0; p < 32; p++) h[p] = __float2half_rn(v[perm_l(p)]);
    uint4* dst = (uint4*)(out + (size_t)r * 1024 + b32 * 32);
#pragma unroll
    for (int i = 0; i < 4; i++) dst[i] = ((const uint4*)h)[i];
}

// ---------------- FFMA rolling LSTM step (fp32-exact, M=256) ---------------
__global__ void __launch_bounds__(256) k_lstm_step(
    const float* __restrict__ Hin, const float* __restrict__ Whh,
    const float* __restrict__ xg, const float* __restrict__ Cin,
    float* __restrict__ Hout, float* __restrict__ Cout, int zeroInit)
{
    constexpr int BM = 64, TM = 4;
    __shared__ float As[16][BM + 4];
    __shared__ float Ws[16][132];
    const int tid = threadIdx.x;
    const int tx = tid & 15, ty = tid >> 4;
    const int m0 = blockIdx.y * BM;
    const int n0 = blockIdx.x * 128;

    float acc[TM][8];
#pragma unroll
    for (int i = 0; i < TM; i++)
#pragma unroll
        for (int j = 0; j < 8; j++) acc[i][j] = 0.f;

    if (!zeroInit) {
        const int lr = tid >> 2;
        const int lk = (tid & 3) << 2;
        for (int kt = 0; kt < 1024; kt += 16) {
            {
                int row = lr;
                float4 v = *(const float4*)&Hin[(size_t)(m0 + row) * 1024 + kt + lk];
                As[lk + 0][row] = v.x; As[lk + 1][row] = v.y;
                As[lk + 2][row] = v.z; As[lk + 3][row] = v.w;
            }
#pragma unroll
            for (int r = 0; r < 2; r++) {
                int wr2 = lr + r * 64;
                int np = n0 + wr2;
                int wrow = ((np & 3) << 10) + (np >> 2);
                float4 v = *(const float4*)&Whh[(size_t)wrow * 1024 + kt + lk];
                Ws[lk + 0][wr2] = v.x; Ws[lk + 1][wr2] = v.y;
                Ws[lk + 2][wr2] = v.z; Ws[lk + 3][wr2] = v.w;
            }
            __syncthreads();
#pragma unroll
            for (int k = 0; k < 16; k++) {
                float a[TM], wv[8];
#pragma unroll
                for (int i = 0; i < TM; i++) a[i] = As[k][ty * TM + i];
#pragma unroll
                for (int j = 0; j < 8; j++) wv[j] = Ws[k][tx * 8 + j];
#pragma unroll
                for (int i = 0; i < TM; i++)
#pragma unroll
                    for (int j = 0; j < 8; j++) acc[i][j] = fmaf(a[i], wv[j], acc[i][j]);
            }
            __syncthreads();
        }
    }

    const int u0 = (n0 + tx * 8) >> 2;
#pragma unroll
    for (int i = 0; i < TM; i++) {
        int m = m0 + ty * TM + i;
        const float* xr = xg + (size_t)m * G4;
#pragma unroll
        for (int uu = 0; uu < 2; uu++) {
            int u = u0 + uu;
            float4 xv = *(const float4*)&xr[(size_t)u * 4];
            float pi = acc[i][uu * 4 + 0] + xv.x;
            float pf = acc[i][uu * 4 + 1] + xv.y;
            float pg = acc[i][uu * 4 + 2] + xv.z;
            float po = acc[i][uu * 4 + 3] + xv.w;
            float c  = zeroInit ? 0.f : Cin[(size_t)m * 1024 + u];
            float c2 = sigf(pf) * c + sigf(pi) * tanhf(pg);
            float h2 = sigf(po) * tanhf(c2);
            Hout[(size_t)m * 1024 + u] = h2;
            Cout[(size_t)m * 1024 + u] = c2;
        }
    }
}

// ---------------- host orchestration ----------------
extern "C" void kernel_launch(void* const* d_in, const int* in_sizes, int n_in,
                              void* d_out, int out_size) {
    (void)in_sizes; (void)n_in; (void)out_size;
    const float* inp   = (const float*)d_in[0];
    const float* Wih_r = (const float*)d_in[1];
    const float* Whh_r = (const float*)d_in[2];
    const float* bih_r = (const float*)d_in[3];
    const float* bhh_r = (const float*)d_in[4];
    const float* Wih_u = (const float*)d_in[5];
    const float* Whh_u = (const float*)d_in[6];
    const float* bih_u = (const float*)d_in[7];
    const float* bhh_u = (const float*)d_in[8];
    const float* Wc    = (const float*)d_in[9];
    const float* bc    = (const float*)d_in[10];
    float* out = (float*)d_out;

    __half *xT, *hu, *hn, *wihr, *wihu, *whhu, *wc;
    float *xg_r, *xg_u, *hs, *cs, *cu;
    int *workp, *cntp;
    cudaGetSymbolAddress((void**)&xT,   g_xT);
    cudaGetSymbolAddress((void**)&xg_r, g_xg_r);
    cudaGetSymbolAddress((void**)&xg_u, g_xg_u);
    cudaGetSymbolAddress((void**)&hs,   g_hs);
    cudaGetSymbolAddress((void**)&cs,   g_cs);
    cudaGetSymbolAddress((void**)&hu,   g_hu);
    cudaGetSymbolAddress((void**)&cu,   g_cu);
    cudaGetSymbolAddress((void**)&hn,   g_hn);
    cudaGetSymbolAddress((void**)&wihr, g_wihr);
    cudaGetSymbolAddress((void**)&wihu, g_wihu);
    cudaGetSymbolAddress((void**)&whhu, g_whhu);
    cudaGetSymbolAddress((void**)&wc,   g_wc);
    cudaGetSymbolAddress((void**)&workp, g_work);
    cudaGetSymbolAddress((void**)&cntp,  g_cnt);
    __half* hu0 = hu;
    __half* hu1 = hu + (size_t)SB * 1024;

    cudaFuncSetAttribute(k_dag,      cudaFuncAttributeMaxDynamicSharedMemorySize, SMEM_LSTM);
    cudaFuncSetAttribute(k_mma_proj, cudaFuncAttributeMaxDynamicSharedMemorySize, SMEM_LIN);

    // 0) prep + fillers (so ncu -s 5 lands on the first proj GEMM)
    k_prep_all<<<(PREP_TOT + 255) / 256, 256>>>(inp, Wih_r, Wih_u, Whh_u, Wc,
                                                xT, wihr, wihu, whhu, wc);
    k_nop<<<1, 32>>>();
    k_nop<<<1, 32>>>();
    k_nop<<<1, 32>>>();

    // 1) input projections
    {
        dim3 g(G4 / 128, SB / 128);
        k_mma_proj<<<g, 256, SMEM_LIN>>>(xT, wihr, xg_r, bih_r, bhh_r);
        k_mma_proj<<<g, 256, SMEM_LIN>>>(xT, wihu, xg_u, bih_u, bhh_u);
    }

    // 2) rolling LSTM: 14 sequential FFMA steps (fp32-exact)
    for (int t = 0; t < S_; t++) {
        dim3 g(G4 / 128, B_ / 64);
        const float* hin = (t == 0) ? nullptr : hs + (size_t)(t - 1) * BH;
        const float* cin = (t == 0) ? nullptr : cs + (size_t)(t - 1) * BH;
        k_lstm_step<<<g, 256>>>(hin, Whh_r,
                                xg_r + (size_t)t * B_ * G4, cin,
                                hs + (size_t)t * BH, cs + (size_t)t * BH,
                                (t == 0) ? 1 : 0);
    }

    // 3) init unroll state + DAG bookkeeping
    k_h2h<<<(SB * 32 + 255) / 256, 256>>>(hs, hu0);
    cudaMemcpyAsync(cu, cs, sizeof(float) * (size_t)SB * 1024, cudaMemcpyDeviceToDevice, 0);
    cudaMemsetAsync(workp, 0, sizeof(int), 0);
    cudaMemsetAsync(cntp, 0, sizeof(int) * NSTEP * 28, 0);

    // 4) all 15 unroll steps + classifier in ONE persistent DAG kernel
    k_dag<<<2 * NSM, 256, SMEM_LSTM>>>(hu0, hu1, whhu, xg_u, cu, hn, wc, bc, out);
}

// round 12
// speedup vs baseline: 1.4606x; 1.4606x over previous
#include <cuda_runtime.h>
#include <cuda_fp16.h>
#include <math.h>
#include <stdint.h>

// ---------------- problem constants ----------------
#define B_ 256
#define S_ 14
#define C_ 2513
#define SB 3584          // S_*B_
#define BH 262144        // B_*H_
#define G4 4096          // 4*H_
#define CLS_NB 20        // ceil(2513/128)

// ---------------- fp16 mma GEMM config (128x128, 256 thr, occ 2) ----------
#define STAGE_H   4096
#define SLOT_H    (2 * STAGE_H)
#define NSTAGE    4
#define MAIN_H    (NSTAGE * SLOT_H)          // 32768 halves = 65536 B
#define SMEM_LSTM ((MAIN_H + 128 * 32) * 2)  // 73728 B
#define SMEM_LIN  (MAIN_H * 2 + 512)         // 66048 B

// ---------------- scratch (device globals) ----------------
__device__ __half g_xT [SB * 1024];
__device__ float  g_xg_r[(size_t)SB * G4];
__device__ float  g_xg_u[(size_t)SB * G4];
__device__ float  g_hs [SB * 1024];
__device__ float  g_cs [SB * 1024];
__device__ __half g_hu [2 * SB * 1024];
__device__ float  g_cu [SB * 1024];
__device__ __half g_hn [SB * 1024];
__device__ __half g_wihr[(size_t)G4 * 1024];
__device__ __half g_wihu[(size_t)G4 * 1024];
__device__ __half g_whhu[(size_t)G4 * 1024];
__device__ __half g_wc [(size_t)2560 * 1024];

__device__ __forceinline__ float sigf(float x) { return 1.0f / (1.0f + expf(-x)); }

// logical-k permutation within each 32-k block
__device__ __forceinline__ int perm_l(int p) {
    int b = (p >> 2) & 1, t = p >> 3, j = p & 3;
    return b * 16 + ((j < 2) ? (2 * t + j) : (2 * t + 8 + (j - 2)));
}
__device__ __forceinline__ int inv_l(int l) {
    int b = l >> 4, r = l & 15, hi = r >> 3, t = (r >> 1) & 3, e = r & 1;
    return t * 8 + b * 4 + hi * 2 + e;
}

// ---------------- low-level helpers ----------------
__device__ __forceinline__ uint32_t smaddr(const void* p) {
    uint32_t a;
    asm("{ .reg .u64 t; cvta.to.shared.u64 t, %1; cvt.u32.u64 %0, t; }" : "=r"(a) : "l"(p));
    return a;
}
__device__ __forceinline__ void cp16(uint32_t d, const void* s) {
    asm volatile("cp.async.cg.shared.global [%0], [%1], 16;" :: "r"(d), "l"(s));
}
__device__ __forceinline__ void cp16z(uint32_t d, const void* s, int sz) {
    asm volatile("cp.async.cg.shared.global [%0], [%1], 16, %2;" :: "r"(d), "l"(s), "r"(sz));
}
__device__ __forceinline__ void cpcommit() { asm volatile("cp.async.commit_group;"); }
template <int N>
__device__ __forceinline__ void cpwait() { asm volatile("cp.async.wait_group %0;" :: "n"(N)); }
__device__ __forceinline__ void mma16(float* d, const uint32_t* a, const uint32_t* b) {
    asm volatile(
        "mma.sync.aligned.m16n8k16.row.col.f32.f16.f16.f32 "
        "{%0,%1,%2,%3},{%4,%5,%6,%7},{%8,%9},{%0,%1,%2,%3};"
        : "+f"(d[0]), "+f"(d[1]), "+f"(d[2]), "+f"(d[3])
        : "r"(a[0]), "r"(a[1]), "r"(a[2]), "r"(a[3]), "r"(b[0]), "r"(b[1]));
}

// ---------------- stage issue (256 threads, 128x32 A + 128x32 B) ----------
template <int EDGE>
__device__ __forceinline__ void stage_issue(
    __half* sm, int slot, const __half* __restrict__ A, const __half* __restrict__ W,
    int m0, int n0, int kt, int Nb, int tid)
{
    __half* dA = sm + slot * SLOT_H;
    __half* dB = dA + STAGE_H;
    const __half* Ap = A + (size_t)m0 * 1024 + kt * 32;
    const __half* Wp = W + (size_t)n0 * 1024 + kt * 32;
#pragma unroll
    for (int i = 0; i < 2; i++) {
        int c = tid + (i << 8);
        int row = c >> 2, c16 = c & 3;
        cp16(smaddr(dA + row * 32 + c16 * 8), Ap + (size_t)row * 1024 + c16 * 8);
        if (EDGE) {
            int ok = (n0 + row < Nb);
            cp16z(smaddr(dB + row * 32 + c16 * 8),
                  Wp + (size_t)(ok ? row : 0) * 1024 + c16 * 8, ok ? 16 : 0);
        } else {
            cp16(smaddr(dB + row * 32 + c16 * 8), Wp + (size_t)row * 1024 + c16 * 8);
        }
    }
    cpcommit();
}

// ---------------- stage compute: 64x32 warp tile, 32 MMAs ------------------
__device__ __forceinline__ void stage_compute(
    const __half* sm, int slot, int wm, int wn, int g, int tig, float acc[4][4][4])
{
    const __half* bA = sm + slot * SLOT_H + (size_t)(wm * 64 + g) * 32 + tig * 8;
    const __half* bB = sm + slot * SLOT_H + STAGE_H + (size_t)(wn * 32 + g) * 32 + tig * 8;
    uint4 bq[4];
#pragma unroll
    for (int ni = 0; ni < 4; ni++)
        bq[ni] = *(const uint4*)(bB + ni * 8 * 32);
#pragma unroll
    for (int mp = 0; mp < 2; mp++) {
        const int m0i = mp * 2, m1i = mp * 2 + 1;
        uint4 alo0 = *(const uint4*)(bA + m0i * 16 * 32);
        uint4 ahi0 = *(const uint4*)(bA + (m0i * 16 + 8) * 32);
        uint4 alo1 = *(const uint4*)(bA + m1i * 16 * 32);
        uint4 ahi1 = *(const uint4*)(bA + (m1i * 16 + 8) * 32);
        uint32_t a00[4] = {alo0.x, ahi0.x, alo0.y, ahi0.y};
        uint32_t a01[4] = {alo0.z, ahi0.z, alo0.w, ahi0.w};
        uint32_t a10[4] = {alo1.x, ahi1.x, alo1.y, ahi1.y};
        uint32_t a11[4] = {alo1.z, ahi1.z, alo1.w, ahi1.w};
#pragma unroll
        for (int ni = 0; ni < 4; ni++) {
            uint32_t bf0[2] = {bq[ni].x, bq[ni].y};
            mma16(acc[m0i][ni], a00, bf0);
        }
#pragma unroll
        for (int ni = 0; ni < 4; ni++) {
            uint32_t bf0[2] = {bq[ni].x, bq[ni].y};
            mma16(acc[m1i][ni], a10, bf0);
        }
#pragma unroll
        for (int ni = 0; ni < 4; ni++) {
            uint32_t bf1[2] = {bq[ni].z, bq[ni].w};
            mma16(acc[m0i][ni], a01, bf1);
        }
#pragma unroll
        for (int ni = 0; ni < 4; ni++) {
            uint32_t bf1[2] = {bq[ni].z, bq[ni].w};
            mma16(acc[m1i][ni], a11, bf1);
        }
    }
}

// ---------------- full K=1024 mainloop (4-stage, 1 sync/iter) --------------
template <int EDGE>
__device__ __forceinline__ void run_mainloop(
    __half* sm, const __half* __restrict__ A, const __half* __restrict__ W,
    int m0, int n0, int Nb, float acc[4][4][4],
    int tid, int wm, int wn, int g, int tig)
{
    stage_issue<EDGE>(sm, 0, A, W, m0, n0, 0, Nb, tid);
    stage_issue<EDGE>(sm, 1, A, W, m0, n0, 1, Nb, tid);
    stage_issue<EDGE>(sm, 2, A, W, m0, n0, 2, Nb, tid);
#pragma unroll 1
    for (int kt = 0; kt < 32; kt++) {
        int slot = kt & 3;
        if (kt < 30)       cpwait<2>();
        else if (kt == 30) cpwait<1>();
        else               cpwait<0>();
        __syncthreads();
        if (kt + 3 < 32) stage_issue<EDGE>(sm, (kt + 3) & 3, A, W, m0, n0, kt + 3, Nb, tid);
        stage_compute(sm, slot, wm, wn, g, tig, acc);
    }
}

// ---------------- classifier tile (device fn, shared by two kernels) -------
__device__ __forceinline__ void cls_tile(
    __half* sm, const __half* __restrict__ hn, const __half* __restrict__ wc,
    const float* __restrict__ bc, float* __restrict__ out,
    int m0, int n0, int tid, int wm, int wn, int g, int tig)
{
    float* biasS = (float*)(sm + MAIN_H);
    if (tid < 128) {
        int np = n0 + tid;
        biasS[tid] = (np < C_) ? bc[np] : 0.f;
    }
    float acc[4][4][4];
#pragma unroll
    for (int a = 0; a < 4; a++)
#pragma unroll
        for (int b = 0; b < 4; b++)
#pragma unroll
            for (int c = 0; c < 4; c++) acc[a][b][c] = 0.f;

    run_mainloop<1>(sm, hn, wc, m0, n0, C_, acc, tid, wm, wn, g, tig);

#pragma unroll
    for (int mi = 0; mi < 4; mi++) {
        const int R0 = m0 + wm * 64 + mi * 16;
#pragma unroll
        for (int ni = 0; ni < 4; ni++) {
            const int v = n0 + wn * 32 + ni * 8 + 2 * tig;
            const float bA0 = biasS[v - n0], bA1 = biasS[v - n0 + 1];
            const int r1 = R0 + g, r2 = R0 + g + 8;
            int or1 = (r1 & 255) * S_ + (r1 >> 8);
            int or2 = (r2 & 255) * S_ + (r2 >> 8);
            if (v < C_) {
                out[(size_t)or1 * C_ + v] = acc[mi][ni][0] + bA0;
                out[(size_t)or2 * C_ + v] = acc[mi][ni][2] + bA0;
            }
            if (v + 1 < C_) {
                out[(size_t)or1 * C_ + v + 1] = acc[mi][ni][1] + bA1;
                out[(size_t)or2 * C_ + v + 1] = acc[mi][ni][3] + bA1;
            }
        }
    }
}

// ---------------- fused LSTM step + piggybacked classifier chunk -----------
__global__ void __launch_bounds__(256, 2) k_mma_lstm(
    const __half* __restrict__ Hin, const __half* __restrict__ Whh,
    const float* __restrict__ xg,
    const float* __restrict__ Cin, float* __restrict__ Cout,
    __half* __restrict__ Hout, __half* __restrict__ hn, int final_t,
    int nact2, int t_cls,
    const __half* __restrict__ wc, const float* __restrict__ bc,
    float* __restrict__ out)
{
    extern __shared__ __half sm[];
    __half* hsm = sm + MAIN_H;
    const int tid = threadIdx.x, lane = tid & 31, wid = tid >> 5;
    const int wm = wid & 1, wn = wid >> 1, g = lane >> 2, tig = lane & 3;

    if ((int)blockIdx.y >= nact2) {
        // classifier chunk for instance t_cls (rows complete in earlier launch)
        if (blockIdx.x >= CLS_NB) return;
        int mb = t_cls * 2 + ((int)blockIdx.y - nact2);
        cls_tile(sm, hn, wc, bc, out, mb * 128, blockIdx.x * 128,
                 tid, wm, wn, g, tig);
        return;
    }

    const int m0 = blockIdx.y * 128, n0 = blockIdx.x * 128;

    float acc[4][4][4];
#pragma unroll
    for (int a = 0; a < 4; a++)
#pragma unroll
        for (int b = 0; b < 4; b++)
#pragma unroll
            for (int c = 0; c < 4; c++) acc[a][b][c] = 0.f;

    run_mainloop<0>(sm, Hin, Whh, m0, n0, 0x7fffffff, acc, tid, wm, wn, g, tig);

#pragma unroll
    for (int mi = 0; mi < 4; mi++) {
        const int R0 = m0 + wm * 64 + mi * 16;
#pragma unroll
        for (int ni = 0; ni < 4; ni++) {
            const int V0 = n0 + wn * 32 + ni * 8;
            float c0 = acc[mi][ni][0], c1 = acc[mi][ni][1];
            float c2 = acc[mi][ni][2], c3 = acc[mi][ni][3];
            int p = tig & 1;
            float x = p ? c0 : c2, y = p ? c1 : c3;
            float sx = __shfl_xor_sync(0xffffffffu, x, 1);
            float sy = __shfl_xor_sync(0xffffffffu, y, 1);
            float pi, pf, pg, po; int row;
            if (!p) { pi = c0; pf = c1; pg = sx; po = sy; row = R0 + g; }
            else    { pi = sx; pf = sy; pg = c2; po = c3; row = R0 + g + 8; }
            int u = (V0 >> 2) + (tig >> 1);
            float4 xv = *(const float4*)(xg + (size_t)row * G4 + u * 4);
            float ci = Cin[(size_t)row * 1024 + u];
            float cn = sigf(pf + xv.y) * ci + sigf(pi + xv.x) * tanhf(pg + xv.z);
            float hv = sigf(po + xv.w) * tanhf(cn);
            Cout[(size_t)row * 1024 + u] = cn;
            int ul = u - (n0 >> 2);
            hsm[(row - m0) * 32 + inv_l(ul)] = __float2half_rn(hv);
        }
    }
    __syncthreads();
    {
        int r = tid >> 1, seg = tid & 1;
        int m = m0 + r;
        const uint4* src = (const uint4*)(hsm + r * 32 + seg * 16);
        uint4 a = src[0], b = src[1];
        __half* gd = Hout + (size_t)m * 1024 + (n0 >> 2) + seg * 16;
        ((uint4*)gd)[0] = a; ((uint4*)gd)[1] = b;
        if ((m >> 8) == final_t) {
            __half* fd = hn + (size_t)m * 1024 + (n0 >> 2) + seg * 16;
            ((uint4*)fd)[0] = a; ((uint4*)fd)[1] = b;
        }
    }
}

// ---------------- standalone classifier chunk (instance t) -----------------
__global__ void __launch_bounds__(256, 2) k_cls(
    const __half* __restrict__ hn, const __half* __restrict__ wc,
    const float* __restrict__ bc, float* __restrict__ out, int t)
{
    extern __shared__ __half sm[];
    const int tid = threadIdx.x, lane = tid & 31, wid = tid >> 5;
    const int wm = wid & 1, wn = wid >> 1, g = lane >> 2, tig = lane & 3;
    int mb = t * 2 + blockIdx.y;
    cls_tile(sm, hn, wc, bc, out, mb * 128, blockIdx.x * 128, tid, wm, wn, g, tig);
}

// ---------------- projection tile (device fn) ------------------------------
__device__ __forceinline__ void proj_tile(
    __half* sm, const __half* __restrict__ A, const __half* __restrict__ W,
    float* __restrict__ Out, const float* __restrict__ b0,
    const float* __restrict__ b1, int m0, int n0,
    int tid, int wm, int wn, int g, int tig)
{
    float* biasS = (float*)(sm + MAIN_H);
    if (tid < 128) {
        int np = n0 + tid;
        int wr = ((np & 3) << 10) | (np >> 2);
        biasS[tid] = b0[wr] + b1[wr];
    }
    float acc[4][4][4];
#pragma unroll
    for (int a = 0; a < 4; a++)
#pragma unroll
        for (int b = 0; b < 4; b++)
#pragma unroll
            for (int c = 0; c < 4; c++) acc[a][b][c] = 0.f;

    run_mainloop<0>(sm, A, W, m0, n0, 0x7fffffff, acc, tid, wm, wn, g, tig);

#pragma unroll
    for (int mi = 0; mi < 4; mi++) {
        const int R0 = m0 + wm * 64 + mi * 16;
#pragma unroll
        for (int ni = 0; ni < 4; ni++) {
            const int v = n0 + wn * 32 + ni * 8 + 2 * tig;
            const float bA0 = biasS[v - n0], bA1 = biasS[v - n0 + 1];
            const int r1 = R0 + g, r2 = R0 + g + 8;
            float2 s1 = make_float2(acc[mi][ni][0] + bA0, acc[mi][ni][1] + bA1);
            float2 s2 = make_float2(acc[mi][ni][2] + bA0, acc[mi][ni][3] + bA1);
            *(float2*)(Out + (size_t)r1 * G4 + v) = s1;
            *(float2*)(Out + (size_t)r2 * G4 + v) = s2;
        }
    }
}

// ---------------- projection kernel (xg_r) ---------------------------------
__global__ void __launch_bounds__(256, 2) k_mma_proj(
    const __half* __restrict__ A, const __half* __restrict__ W,
    float* __restrict__ Out, const float* __restrict__ b0,
    const float* __restrict__ b1)
{
    extern __shared__ __half sm[];
    const int tid = threadIdx.x, lane = tid & 31, wid = tid >> 5;
    const int wm = wid & 1, wn = wid >> 1, g = lane >> 2, tig = lane & 3;
    proj_tile(sm, A, W, Out, b0, b1, blockIdx.y * 128, blockIdx.x * 128,
              tid, wm, wn, g, tig);
}

// ---------------- merged rolling step + proj_u slice ------------------------
// blockIdx.y < 4 : FFMA rolling tile (m0 = by*64)
// blockIdx.y >= 4: proj_u tile (m-block = slice*2 + (by-4))
__global__ void __launch_bounds__(256, 2) k_roll_proj(
    const float* __restrict__ Hin, const float* __restrict__ Whh,
    const float* __restrict__ xg, const float* __restrict__ Cin,
    float* __restrict__ Hout, float* __restrict__ Cout, int zeroInit,
    const __half* __restrict__ xT, const __half* __restrict__ wihu,
    float* __restrict__ xg_u, const float* __restrict__ bih_u,
    const float* __restrict__ bhh_u, int slice)
{
    extern __shared__ __half dsm[];
    const int tid = threadIdx.x;

    if (blockIdx.y >= 4) {
        const int lane = tid & 31, wid = tid >> 5;
        const int wm = wid & 1, wn = wid >> 1, g = lane >> 2, tig = lane & 3;
        int mb = slice * 2 + ((int)blockIdx.y - 4);
        proj_tile(dsm, xT, wihu, xg_u, bih_u, bhh_u,
                  mb * 128, blockIdx.x * 128, tid, wid & 1, wid >> 1, g, tig);
        (void)wm; (void)wn;
        return;
    }

    // ---- FFMA rolling tile ----
    constexpr int BM = 64, TM = 4;
    __shared__ float As[16][BM + 4];
    __shared__ float Ws[16][132];
    const int tx = tid & 15, ty = tid >> 4;
    const int m0 = blockIdx.y * BM;
    const int n0 = blockIdx.x * 128;

    float acc[TM][8];
#pragma unroll
    for (int i = 0; i < TM; i++)
#pragma unroll
        for (int j = 0; j < 8; j++) acc[i][j] = 0.f;

    if (!zeroInit) {
        const int lr = tid >> 2;
        const int lk = (tid & 3) << 2;
        for (int kt = 0; kt < 1024; kt += 16) {
            {
                int row = lr;
                float4 v = *(const float4*)&Hin[(size_t)(m0 + row) * 1024 + kt + lk];
                As[lk + 0][row] = v.x; As[lk + 1][row] = v.y;
                As[lk + 2][row] = v.z; As[lk + 3][row] = v.w;
            }
#pragma unroll
            for (int r = 0; r < 2; r++) {
                int wr2 = lr + r * 64;
                int np = n0 + wr2;
                int wrow = ((np & 3) << 10) + (np >> 2);
                float4 v = *(const float4*)&Whh[(size_t)wrow * 1024 + kt + lk];
                Ws[lk + 0][wr2] = v.x; Ws[lk + 1][wr2] = v.y;
                Ws[lk + 2][wr2] = v.z; Ws[lk + 3][wr2] = v.w;
            }
            __syncthreads();
#pragma unroll
            for (int k = 0; k < 16; k++) {
                float a[TM], wv[8];
#pragma unroll
                for (int i = 0; i < TM; i++) a[i] = As[k][ty * TM + i];
#pragma unroll
                for (int j = 0; j < 8; j++) wv[j] = Ws[k][tx * 8 + j];
#pragma unroll
                for (int i = 0; i < TM; i++)
#pragma unroll
                    for (int j = 0; j < 8; j++) acc[i][j] = fmaf(a[i], wv[j], acc[i][j]);
            }
            __syncthreads();
        }
    }

    const int u0 = (n0 + tx * 8) >> 2;
#pragma unroll
    for (int i = 0; i < TM; i++) {
        int m = m0 + ty * TM + i;
        const float* xr = xg + (size_t)m * G4;
#pragma unroll
        for (int uu = 0; uu < 2; uu++) {
            int u = u0 + uu;
            float4 xv = *(const float4*)&xr[(size_t)u * 4];
            float pi = acc[i][uu * 4 + 0] + xv.x;
            float pf = acc[i][uu * 4 + 1] + xv.y;
            float pg = acc[i][uu * 4 + 2] + xv.z;
            float po = acc[i][uu * 4 + 3] + xv.w;
            float c  = zeroInit ? 0.f : Cin[(size_t)m * 1024 + u];
            float c2 = sigf(pf) * c + sigf(pi) * tanhf(pg);
            float h2 = sigf(po) * tanhf(c2);
            Hout[(size_t)m * 1024 + u] = h2;
            Cout[(size_t)m * 1024 + u] = c2;
        }
    }
}

// ---------------- merged prep kernel (fp32 -> fp16 + k-permute) ------------
#define PREP_XT   (SB * 32)
#define PREP_W    (G4 * 32)
#define PREP_WC   (C_ * 32)
#define PREP_TOT  (PREP_XT + 3 * PREP_W + PREP_WC)

__global__ void k_prep_all(
    const float* __restrict__ inp,
    const float* __restrict__ Wih_r, const float* __restrict__ Wih_u,
    const float* __restrict__ Whh_u, const float* __restrict__ Wc,
    __half* __restrict__ xT, __half* __restrict__ wihr, __half* __restrict__ wihu,
    __half* __restrict__ whhu, __half* __restrict__ wc)
{
    int idx = blockIdx.x * blockDim.x + threadIdx.x;
    if (idx >= PREP_TOT) return;
    const float* src;
    __half* dstbase;
    int r, b32;
    if (idx < PREP_XT) {
        r = idx >> 5; b32 = idx & 31;
        int b = r % B_, s = r / B_;
        src = inp + (size_t)(b * S_ + s) * 1024 + b32 * 32;
        dstbase = xT;
    } else {
        int t = idx - PREP_XT;
        int seg = t / PREP_W;
        if (seg < 3) {
            int u = t - seg * PREP_W;
            r = u >> 5; b32 = u & 31;
            int wr = ((r & 3) << 10) | (r >> 2);
            const float* W = (seg == 0) ? Wih_r : (seg == 1) ? Wih_u : Whh_u;
            src = W + (size_t)wr * 1024 + b32 * 32;
            dstbase = (seg == 0) ? wihr : (seg == 1) ? wihu : whhu;
        } else {
            int u = t - 3 * PREP_W;
            r = u >> 5; b32 = u & 31;
            src = Wc + (size_t)r * 1024 + b32 * 32;
            dstbase = wc;
        }
    }
    float v[32];
#pragma unroll
    for (int i = 0; i < 8; i++) *(float4*)&v[i * 4] = *(const float4*)(src + i * 4);
    __half h[32];
#pragma unroll
    for (int p = 0; p < 32; p++) h[p] = __float2half_rn(v[perm_l(p)]);
    uint4* dst = (uint4*)(dstbase + (size_t)r * 1024 + b32 * 32);
#pragma unroll
    for (int i = 0; i < 4; i++) dst[i] = ((const uint4*)h)[i];
}

// h (fp32 logical) -> fp16 permuted
__global__ void k_h2h(const float* __restrict__ in, __half* __restrict__ out) {
    int idx = blockIdx.x * blockDim.x + threadIdx.x;
    if (idx >= SB * 32) return;
    int r = idx >> 5, b32 = idx & 31;
    const float* src = in + (size_t)r * 1024 + b32 * 32;
    float v[32];
#pragma unroll
    for (int i = 0; i < 8; i++) *(float4*)&v[i * 4] = *(const float4*)(src + i * 4);
    __half h[32];
#pragma unroll
    for (int p = 0; p < 32; p++) h[p] = __float2half_rn(v[perm_l(p)]);
    uint4* dst = (uint4*)(out + (size_t)r * 1024 + b32 * 32);
#pragma unroll
    for (int i = 0; i < 4; i++) dst[i] = ((const uint4*)h)[i];
}

// ---------------- host orchestration ----------------
extern "C" void kernel_launch(void* const* d_in, const int* in_sizes, int n_in,
                              void* d_out, int out_size) {
    (void)in_sizes; (void)n_in; (void)out_size;
    const float* inp   = (const float*)d_in[0];
    const float* Wih_r = (const float*)d_in[1];
    const float* Whh_r = (const float*)d_in[2];
    const float* bih_r = (const float*)d_in[3];
    const float* bhh_r = (const float*)d_in[4];
    const float* Wih_u = (const float*)d_in[5];
    const float* Whh_u = (const float*)d_in[6];
    const float* bih_u = (const float*)d_in[7];
    const float* bhh_u = (const float*)d_in[8];
    const float* Wc    = (const float*)d_in[9];
    const float* bc    = (const float*)d_in[10];
    float* out = (float*)d_out;

    __half *xT, *hu, *hn, *wihr, *wihu, *whhu, *wc;
    float *xg_r, *xg_u, *hs, *cs, *cu;
    cudaGetSymbolAddress((void**)&xT,   g_xT);
    cudaGetSymbolAddress((void**)&xg_r, g_xg_r);
    cudaGetSymbolAddress((void**)&xg_u, g_xg_u);
    cudaGetSymbolAddress((void**)&hs,   g_hs);
    cudaGetSymbolAddress((void**)&cs,   g_cs);
    cudaGetSymbolAddress((void**)&hu,   g_hu);
    cudaGetSymbolAddress((void**)&cu,   g_cu);
    cudaGetSymbolAddress((void**)&hn,   g_hn);
    cudaGetSymbolAddress((void**)&wihr, g_wihr);
    cudaGetSymbolAddress((void**)&wihu, g_wihu);
    cudaGetSymbolAddress((void**)&whhu, g_whhu);
    cudaGetSymbolAddress((void**)&wc,   g_wc);
    __half* hu0 = hu;
    __half* hu1 = hu + (size_t)SB * 1024;

    cudaFuncSetAttribute(k_mma_lstm,  cudaFuncAttributeMaxDynamicSharedMemorySize, SMEM_LSTM);
    cudaFuncSetAttribute(k_mma_proj,  cudaFuncAttributeMaxDynamicSharedMemorySize, SMEM_LIN);
    cudaFuncSetAttribute(k_roll_proj, cudaFuncAttributeMaxDynamicSharedMemorySize, SMEM_LIN);
    cudaFuncSetAttribute(k_cls,       cudaFuncAttributeMaxDynamicSharedMemorySize, SMEM_LIN);

    // 0) prep: all operands -> fp16 (+permute)
    k_prep_all<<<(PREP_TOT + 255) / 256, 256>>>(inp, Wih_r, Wih_u, Whh_u, Wc,
                                                xT, wihr, wihu, whhu, wc);

    // 1) rolling projection xg_r (needed before rolling step 0)
    {
        dim3 g(G4 / 128, SB / 128);
        k_mma_proj<<<g, 256, SMEM_LIN>>>(xT, wihr, xg_r, bih_r, bhh_r);
    }

    // 2) rolling LSTM (14 steps), each carrying a 64-tile slice of proj_u
    for (int t = 0; t < S_; t++) {
        dim3 g(G4 / 128, 4 + 2);
        const float* hin = (t == 0) ? nullptr : hs + (size_t)(t - 1) * BH;
        const float* cin = (t == 0) ? nullptr : cs + (size_t)(t - 1) * BH;
        k_roll_proj<<<g, 256, SMEM_LIN>>>(hin, Whh_r,
                                          xg_r + (size_t)t * B_ * G4, cin,
                                          hs + (size_t)t * BH, cs + (size_t)t * BH,
                                          (t == 0) ? 1 : 0,
                                          xT, wihu, xg_u, bih_u, bhh_u, t);
    }

    // 3) unroll h init (fp16 permuted); c: step 0 reads cs directly
    k_h2h<<<(SB * 32 + 255) / 256, 256>>>(hs, hu0);

    // 4) unroll LSTM: 15 steps; steps j>=2 carry classifier chunk for t=15-j
    for (int j = 0; j <= S_; j++) {
        int nact = (15 - j < 14) ? (15 - j) : 14;
        const __half* hin = (j & 1) ? hu1 : hu0;
        __half*       ho  = (j & 1) ? hu0 : hu1;
        const float*  cin = (j == 0) ? cs : cu;
        int final_t = S_ - j;
        int t_cls = (j >= 2) ? (15 - j) : -1;
        dim3 g(G4 / 128, nact * 2 + ((t_cls >= 0) ? 2 : 0));
        k_mma_lstm<<<g, 256, SMEM_LSTM>>>(hin, whhu, xg_u, cin, cu, ho, hn,
                                          final_t, nact * 2, t_cls, wc, bc, out);
    }

    // 5) final classifier chunk (instance t=0)
    {
        dim3 g(CLS_NB, 2);
        k_cls<<<g, 256, SMEM_LIN>>>(hn, wc, bc, out, 0);
    }
}

// round 13
// speedup vs baseline: 1.4742x; 1.0093x over previous
#include <cuda_runtime.h>
#include <cuda_fp16.h>
#include <math.h>
#include <stdint.h>

// ---------------- problem constants ----------------
#define B_ 256
#define S_ 14
#define C_ 2513
#define SB 3584          // S_*B_
#define BH 262144        // B_*H_
#define G4 4096          // 4*H_
#define CLS_NB 20        // ceil(2513/128)

// ---------------- fp16 mma GEMM config (128x128, 256 thr, occ 2) ----------
#define STAGE_H   4096
#define SLOT_H    (2 * STAGE_H)
#define NSTAGE    4
#define MAIN_H    (NSTAGE * SLOT_H)          // 32768 halves = 65536 B
#define SMEM_LSTM ((MAIN_H + 128 * 32) * 2)  // 73728 B
#define SMEM_LIN  (MAIN_H * 2 + 512)         // 66048 B

// ---------------- scratch (device globals) ----------------
__device__ __half g_xT [SB * 1024];
__device__ float  g_xg_r[(size_t)SB * G4];
__device__ float  g_xg_u[(size_t)SB * G4];
__device__ float  g_hs [SB * 1024];
__device__ float  g_cs [SB * 1024];
__device__ __half g_hu [2 * SB * 1024];
__device__ float  g_cu [SB * 1024];
__device__ __half g_hn [SB * 1024];
__device__ __half g_wihr[(size_t)G4 * 1024];
__device__ __half g_wihu[(size_t)G4 * 1024];
__device__ __half g_whhu[(size_t)G4 * 1024];
__device__ __half g_wc [(size_t)2560 * 1024];

__device__ __forceinline__ float sigf(float x) { return 1.0f / (1.0f + expf(-x)); }

// logical-k permutation within each 32-k block
__device__ __forceinline__ int perm_l(int p) {
    int b = (p >> 2) & 1, t = p >> 3, j = p & 3;
    return b * 16 + ((j < 2) ? (2 * t + j) : (2 * t + 8 + (j - 2)));
}
__device__ __forceinline__ int inv_l(int l) {
    int b = l >> 4, r = l & 15, hi = r >> 3, t = (r >> 1) & 3, e = r & 1;
    return t * 8 + b * 4 + hi * 2 + e;
}

// ---------------- low-level helpers ----------------
__device__ __forceinline__ uint32_t smaddr(const void* p) {
    uint32_t a;
    asm("{ .reg .u64 t; cvta.to.shared.u64 t, %1; cvt.u32.u64 %0, t; }" : "=r"(a) : "l"(p));
    return a;
}
__device__ __forceinline__ void cp16(uint32_t d, const void* s) {
    asm volatile("cp.async.cg.shared.global [%0], [%1], 16;" :: "r"(d), "l"(s));
}
__device__ __forceinline__ void cp16z(uint32_t d, const void* s, int sz) {
    asm volatile("cp.async.cg.shared.global [%0], [%1], 16, %2;" :: "r"(d), "l"(s), "r"(sz));
}
__device__ __forceinline__ void cpcommit() { asm volatile("cp.async.commit_group;"); }
template <int N>
__device__ __forceinline__ void cpwait() { asm volatile("cp.async.wait_group %0;" :: "n"(N)); }
__device__ __forceinline__ void mma16(float* d, const uint32_t* a, const uint32_t* b) {
    asm volatile(
        "mma.sync.aligned.m16n8k16.row.col.f32.f16.f16.f32 "
        "{%0,%1,%2,%3},{%4,%5,%6,%7},{%8,%9},{%0,%1,%2,%3};"
        : "+f"(d[0]), "+f"(d[1]), "+f"(d[2]), "+f"(d[3])
        : "r"(a[0]), "r"(a[1]), "r"(a[2]), "r"(a[3]), "r"(b[0]), "r"(b[1]));
}

// ---------------- stage issue (256 threads, 128x32 A + 128x32 B) ----------
template <int EDGE>
__device__ __forceinline__ void stage_issue(
    __half* sm, int slot, const __half* __restrict__ A, const __half* __restrict__ W,
    int m0, int n0, int kt, int Nb, int tid)
{
    __half* dA = sm + slot * SLOT_H;
    __half* dB = dA + STAGE_H;
    const __half* Ap = A + (size_t)m0 * 1024 + kt * 32;
    const __half* Wp = W + (size_t)n0 * 1024 + kt * 32;
#pragma unroll
    for (int i = 0; i < 2; i++) {
        int c = tid + (i << 8);
        int row = c >> 2, c16 = c & 3;
        cp16(smaddr(dA + row * 32 + c16 * 8), Ap + (size_t)row * 1024 + c16 * 8);
        if (EDGE) {
            int ok = (n0 + row < Nb);
            cp16z(smaddr(dB + row * 32 + c16 * 8),
                  Wp + (size_t)(ok ? row : 0) * 1024 + c16 * 8, ok ? 16 : 0);
        } else {
            cp16(smaddr(dB + row * 32 + c16 * 8), Wp + (size_t)row * 1024 + c16 * 8);
        }
    }
    cpcommit();
}

// ---------------- stage compute: 64x32 warp tile, 32 MMAs ------------------
__device__ __forceinline__ void stage_compute(
    const __half* sm, int slot, int wm, int wn, int g, int tig, float acc[4][4][4])
{
    const __half* bA = sm + slot * SLOT_H + (size_t)(wm * 64 + g) * 32 + tig * 8;
    const __half* bB = sm + slot * SLOT_H + STAGE_H + (size_t)(wn * 32 + g) * 32 + tig * 8;
    uint4 bq[4];
#pragma unroll
    for (int ni = 0; ni < 4; ni++)
        bq[ni] = *(const uint4*)(bB + ni * 8 * 32);
#pragma unroll
    for (int mp = 0; mp < 2; mp++) {
        const int m0i = mp * 2, m1i = mp * 2 + 1;
        uint4 alo0 = *(const uint4*)(bA + m0i * 16 * 32);
        uint4 ahi0 = *(const uint4*)(bA + (m0i * 16 + 8) * 32);
        uint4 alo1 = *(const uint4*)(bA + m1i * 16 * 32);
        uint4 ahi1 = *(const uint4*)(bA + (m1i * 16 + 8) * 32);
        uint32_t a00[4] = {alo0.x, ahi0.x, alo0.y, ahi0.y};
        uint32_t a01[4] = {alo0.z, ahi0.z, alo0.w, ahi0.w};
        uint32_t a10[4] = {alo1.x, ahi1.x, alo1.y, ahi1.y};
        uint32_t a11[4] = {alo1.z, ahi1.z, alo1.w, ahi1.w};
#pragma unroll
        for (int ni = 0; ni < 4; ni++) {
            uint32_t bf0[2] = {bq[ni].x, bq[ni].y};
            mma16(acc[m0i][ni], a00, bf0);
        }
#pragma unroll
        for (int ni = 0; ni < 4; ni++) {
            uint32_t bf0[2] = {bq[ni].x, bq[ni].y};
            mma16(acc[m1i][ni], a10, bf0);
        }
#pragma unroll
        for (int ni = 0; ni < 4; ni++) {
            uint32_t bf1[2] = {bq[ni].z, bq[ni].w};
            mma16(acc[m0i][ni], a01, bf1);
        }
#pragma unroll
        for (int ni = 0; ni < 4; ni++) {
            uint32_t bf1[2] = {bq[ni].z, bq[ni].w};
            mma16(acc[m1i][ni], a11, bf1);
        }
    }
}

// ---------------- full K=1024 mainloop (4-stage, 1 sync/iter) --------------
template <int EDGE>
__device__ __forceinline__ void run_mainloop(
    __half* sm, const __half* __restrict__ A, const __half* __restrict__ W,
    int m0, int n0, int Nb, float acc[4][4][4],
    int tid, int wm, int wn, int g, int tig)
{
    stage_issue<EDGE>(sm, 0, A, W, m0, n0, 0, Nb, tid);
    stage_issue<EDGE>(sm, 1, A, W, m0, n0, 1, Nb, tid);
    stage_issue<EDGE>(sm, 2, A, W, m0, n0, 2, Nb, tid);
#pragma unroll 1
    for (int kt = 0; kt < 32; kt++) {
        int slot = kt & 3;
        if (kt < 30)       cpwait<2>();
        else if (kt == 30) cpwait<1>();
        else               cpwait<0>();
        __syncthreads();
        if (kt + 3 < 32) stage_issue<EDGE>(sm, (kt + 3) & 3, A, W, m0, n0, kt + 3, Nb, tid);
        stage_compute(sm, slot, wm, wn, g, tig, acc);
    }
}

// ---------------- classifier tile (device fn) -------------------------------
__device__ __forceinline__ void cls_tile(
    __half* sm, const __half* __restrict__ hn, const __half* __restrict__ wc,
    const float* __restrict__ bc, float* __restrict__ out,
    int m0, int n0, int tid, int wm, int wn, int g, int tig)
{
    float* biasS = (float*)(sm + MAIN_H);
    if (tid < 128) {
        int np = n0 + tid;
        biasS[tid] = (np < C_) ? bc[np] : 0.f;
    }
    float acc[4][4][4];
#pragma unroll
    for (int a = 0; a < 4; a++)
#pragma unroll
        for (int b = 0; b < 4; b++)
#pragma unroll
            for (int c = 0; c < 4; c++) acc[a][b][c] = 0.f;

    run_mainloop<1>(sm, hn, wc, m0, n0, C_, acc, tid, wm, wn, g, tig);

#pragma unroll
    for (int mi = 0; mi < 4; mi++) {
        const int R0 = m0 + wm * 64 + mi * 16;
#pragma unroll
        for (int ni = 0; ni < 4; ni++) {
            const int v = n0 + wn * 32 + ni * 8 + 2 * tig;
            const float bA0 = biasS[v - n0], bA1 = biasS[v - n0 + 1];
            const int r1 = R0 + g, r2 = R0 + g + 8;
            int or1 = (r1 & 255) * S_ + (r1 >> 8);
            int or2 = (r2 & 255) * S_ + (r2 >> 8);
            if (v < C_) {
                out[(size_t)or1 * C_ + v] = acc[mi][ni][0] + bA0;
                out[(size_t)or2 * C_ + v] = acc[mi][ni][2] + bA0;
            }
            if (v + 1 < C_) {
                out[(size_t)or1 * C_ + v + 1] = acc[mi][ni][1] + bA1;
                out[(size_t)or2 * C_ + v + 1] = acc[mi][ni][3] + bA1;
            }
        }
    }
}

// ---------------- fused LSTM step + piggybacked classifier chunk -----------
__global__ void __launch_bounds__(256, 2) k_mma_lstm(
    const __half* __restrict__ Hin, const __half* __restrict__ Whh,
    const float* __restrict__ xg,
    const float* __restrict__ Cin, float* __restrict__ Cout,
    __half* __restrict__ Hout, __half* __restrict__ hn, int final_t,
    int nact2, int t_cls,
    const __half* __restrict__ wc, const float* __restrict__ bc,
    float* __restrict__ out)
{
    extern __shared__ __half sm[];
    __half* hsm = sm + MAIN_H;
    const int tid = threadIdx.x, lane = tid & 31, wid = tid >> 5;
    const int wm = wid & 1, wn = wid >> 1, g = lane >> 2, tig = lane & 3;

    if ((int)blockIdx.y >= nact2) {
        // classifier chunk for instance t_cls (rows finalized in launch j-1)
        if (blockIdx.x >= CLS_NB) return;
        int mb = t_cls * 2 + ((int)blockIdx.y - nact2);
        cls_tile(sm, hn, wc, bc, out, mb * 128, blockIdx.x * 128,
                 tid, wm, wn, g, tig);
        return;
    }

    const int m0 = blockIdx.y * 128, n0 = blockIdx.x * 128;

    float acc[4][4][4];
#pragma unroll
    for (int a = 0; a < 4; a++)
#pragma unroll
        for (int b = 0; b < 4; b++)
#pragma unroll
            for (int c = 0; c < 4; c++) acc[a][b][c] = 0.f;

    run_mainloop<0>(sm, Hin, Whh, m0, n0, 0x7fffffff, acc, tid, wm, wn, g, tig);

#pragma unroll
    for (int mi = 0; mi < 4; mi++) {
        const int R0 = m0 + wm * 64 + mi * 16;
#pragma unroll
        for (int ni = 0; ni < 4; ni++) {
            const int V0 = n0 + wn * 32 + ni * 8;
            float c0 = acc[mi][ni][0], c1 = acc[mi][ni][1];
            float c2 = acc[mi][ni][2], c3 = acc[mi][ni][3];
            int p = tig & 1;
            float x = p ? c0 : c2, y = p ? c1 : c3;
            float sx = __shfl_xor_sync(0xffffffffu, x, 1);
            float sy = __shfl_xor_sync(0xffffffffu, y, 1);
            float pi, pf, pg, po; int row;
            if (!p) { pi = c0; pf = c1; pg = sx; po = sy; row = R0 + g; }
            else    { pi = sx; pf = sy; pg = c2; po = c3; row = R0 + g + 8; }
            int u = (V0 >> 2) + (tig >> 1);
            float4 xv = *(const float4*)(xg + (size_t)row * G4 + u * 4);
            float ci = Cin[(size_t)row * 1024 + u];
            float cn = sigf(pf + xv.y) * ci + sigf(pi + xv.x) * tanhf(pg + xv.z);
            float hv = sigf(po + xv.w) * tanhf(cn);
            Cout[(size_t)row * 1024 + u] = cn;
            int ul = u - (n0 >> 2);
            hsm[(row - m0) * 32 + inv_l(ul)] = __float2half_rn(hv);
        }
    }
    __syncthreads();
    {
        int r = tid >> 1, seg = tid & 1;
        int m = m0 + r;
        const uint4* src = (const uint4*)(hsm + r * 32 + seg * 16);
        uint4 a = src[0], b = src[1];
        __half* gd = Hout + (size_t)m * 1024 + (n0 >> 2) + seg * 16;
        ((uint4*)gd)[0] = a; ((uint4*)gd)[1] = b;
        if ((m >> 8) == final_t) {
            __half* fd = hn + (size_t)m * 1024 + (n0 >> 2) + seg * 16;
            ((uint4*)fd)[0] = a; ((uint4*)fd)[1] = b;
        }
    }
}

// ---------------- standalone classifier chunk (instance t) -----------------
__global__ void __launch_bounds__(256, 2) k_cls(
    const __half* __restrict__ hn, const __half* __restrict__ wc,
    const float* __restrict__ bc, float* __restrict__ out, int t)
{
    extern __shared__ __half sm[];
    const int tid = threadIdx.x, lane = tid & 31, wid = tid >> 5;
    const int wm = wid & 1, wn = wid >> 1, g = lane >> 2, tig = lane & 3;
    int mb = t * 2 + blockIdx.y;
    cls_tile(sm, hn, wc, bc, out, mb * 128, blockIdx.x * 128, tid, wm, wn, g, tig);
}

// ---------------- merged projections (blockIdx.z selects r/u set) ----------
__global__ void __launch_bounds__(256, 2) k_mma_proj(
    const __half* __restrict__ A,
    const __half* __restrict__ W0, float* __restrict__ O0,
    const float* __restrict__ b00, const float* __restrict__ b01,
    const __half* __restrict__ W1, float* __restrict__ O1,
    const float* __restrict__ b10, const float* __restrict__ b11)
{
    extern __shared__ __half sm[];
    float* biasS = (float*)(sm + MAIN_H);
    const int tid = threadIdx.x, lane = tid & 31, wid = tid >> 5;
    const int wm = wid & 1, wn = wid >> 1, g = lane >> 2, tig = lane & 3;
    const int m0 = blockIdx.y * 128, n0 = blockIdx.x * 128;
    const int sel = blockIdx.z;
    const __half* W = sel ? W1 : W0;
    float* Out = sel ? O1 : O0;
    const float* b0 = sel ? b10 : b00;
    const float* b1 = sel ? b11 : b01;

    if (tid < 128) {
        int np = n0 + tid;
        int wr = ((np & 3) << 10) | (np >> 2);
        biasS[tid] = b0[wr] + b1[wr];
    }

    float acc[4][4][4];
#pragma unroll
    for (int a = 0; a < 4; a++)
#pragma unroll
        for (int b = 0; b < 4; b++)
#pragma unroll
            for (int c = 0; c < 4; c++) acc[a][b][c] = 0.f;

    run_mainloop<0>(sm, A, W, m0, n0, 0x7fffffff, acc, tid, wm, wn, g, tig);

#pragma unroll
    for (int mi = 0; mi < 4; mi++) {
        const int R0 = m0 + wm * 64 + mi * 16;
#pragma unroll
        for (int ni = 0; ni < 4; ni++) {
            const int v = n0 + wn * 32 + ni * 8 + 2 * tig;
            const float bA0 = biasS[v - n0], bA1 = biasS[v - n0 + 1];
            const int r1 = R0 + g, r2 = R0 + g + 8;
            float2 s1 = make_float2(acc[mi][ni][0] + bA0, acc[mi][ni][1] + bA1);
            float2 s2 = make_float2(acc[mi][ni][2] + bA0, acc[mi][ni][3] + bA1);
            *(float2*)(Out + (size_t)r1 * G4 + v) = s1;
            *(float2*)(Out + (size_t)r2 * G4 + v) = s2;
        }
    }
}

// ---------------- merged prep kernel (fp32 -> fp16 + k-permute) ------------
#define PREP_XT   (SB * 32)
#define PREP_W    (G4 * 32)
#define PREP_WC   (C_ * 32)
#define PREP_TOT  (PREP_XT + 3 * PREP_W + PREP_WC)

__global__ void k_prep_all(
    const float* __restrict__ inp,
    const float* __restrict__ Wih_r, const float* __restrict__ Wih_u,
    const float* __restrict__ Whh_u, const float* __restrict__ Wc,
    __half* __restrict__ xT, __half* __restrict__ wihr, __half* __restrict__ wihu,
    __half* __restrict__ whhu, __half* __restrict__ wc)
{
    int idx = blockIdx.x * blockDim.x + threadIdx.x;
    if (idx >= PREP_TOT) return;
    const float* src;
    __half* dstbase;
    int r, b32;
    if (idx < PREP_XT) {
        r = idx >> 5; b32 = idx & 31;
        int b = r % B_, s = r / B_;
        src = inp + (size_t)(b * S_ + s) * 1024 + b32 * 32;
        dstbase = xT;
    } else {
        int t = idx - PREP_XT;
        int seg = t / PREP_W;
        if (seg < 3) {
            int u = t - seg * PREP_W;
            r = u >> 5; b32 = u & 31;
            int wr = ((r & 3) << 10) | (r >> 2);
            const float* W = (seg == 0) ? Wih_r : (seg == 1) ? Wih_u : Whh_u;
            src = W + (size_t)wr * 1024 + b32 * 32;
            dstbase = (seg == 0) ? wihr : (seg == 1) ? wihu : whhu;
        } else {
            int u = t - 3 * PREP_W;
            r = u >> 5; b32 = u & 31;
            src = Wc + (size_t)r * 1024 + b32 * 32;
            dstbase = wc;
        }
    }
    float v[32];
#pragma unroll
    for (int i = 0; i < 8; i++) *(float4*)&v[i * 4] = *(const float4*)(src + i * 4);
    __half h[32];
#pragma unroll
    for (int p = 0; p < 32; p++) h[p] = __float2half_rn(v[perm_l(p)]);
    uint4* dst = (uint4*)(dstbase + (size_t)r * 1024 + b32 * 32);
#pragma unroll
    for (int i = 0; i < 4; i++) dst[i] = ((const uint4*)h)[i];
}

// h (fp32 logical) -> fp16 permuted
__global__ void k_h2h(const float* __restrict__ in, __half* __restrict__ out) {
    int idx = blockIdx.x * blockDim.x + threadIdx.x;
    if (idx >= SB * 32) return;
    int r = idx >> 5, b32 = idx & 31;
    const float* src = in + (size_t)r * 1024 + b32 * 32;
    float v[32];
#pragma unroll
    for (int i = 0; i < 8; i++) *(float4*)&v[i * 4] = *(const float4*)(src + i * 4);
    __half h[32];
#pragma unroll
    for (int p = 0; p < 32; p++) h[p] = __float2half_rn(v[perm_l(p)]);
    uint4* dst = (uint4*)(out + (size_t)r * 1024 + b32 * 32);
#pragma unroll
    for (int i = 0; i < 4; i++) dst[i] = ((const uint4*)h)[i];
}

// ---------------- FFMA rolling LSTM step (fp32-exact, M=256) ---------------
__global__ void __launch_bounds__(256) k_lstm_step(
    const float* __restrict__ Hin, const float* __restrict__ Whh,
    const float* __restrict__ xg, const float* __restrict__ Cin,
    float* __restrict__ Hout, float* __restrict__ Cout, int zeroInit)
{
    constexpr int BM = 64, TM = 4;
    __shared__ float As[16][BM + 4];
    __shared__ float Ws[16][132];
    const int tid = threadIdx.x;
    const int tx = tid & 15, ty = tid >> 4;
    const int m0 = blockIdx.y * BM;
    const int n0 = blockIdx.x * 128;

    float acc[TM][8];
#pragma unroll
    for (int i = 0; i < TM; i++)
#pragma unroll
        for (int j = 0; j < 8; j++) acc[i][j] = 0.f;

    if (!zeroInit) {
        const int lr = tid >> 2;
        const int lk = (tid & 3) << 2;
        for (int kt = 0; kt < 1024; kt += 16) {
            {
                int row = lr;
                float4 v = *(const float4*)&Hin[(size_t)(m0 + row) * 1024 + kt + lk];
                As[lk + 0][row] = v.x; As[lk + 1][row] = v.y;
                As[lk + 2][row] = v.z; As[lk + 3][row] = v.w;
            }
#pragma unroll
            for (int r = 0; r < 2; r++) {
                int wr2 = lr + r * 64;
                int np = n0 + wr2;
                int wrow = ((np & 3) << 10) + (np >> 2);
                float4 v = *(const float4*)&Whh[(size_t)wrow * 1024 + kt + lk];
                Ws[lk + 0][wr2] = v.x; Ws[lk + 1][wr2] = v.y;
                Ws[lk + 2][wr2] = v.z; Ws[lk + 3][wr2] = v.w;
            }
            __syncthreads();
#pragma unroll
            for (int k = 0; k < 16; k++) {
                float a[TM], wv[8];
#pragma unroll
                for (int i = 0; i < TM; i++) a[i] = As[k][ty * TM + i];
#pragma unroll
                for (int j = 0; j < 8; j++) wv[j] = Ws[k][tx * 8 + j];
#pragma unroll
                for (int i = 0; i < TM; i++)
#pragma unroll
                    for (int j = 0; j < 8; j++) acc[i][j] = fmaf(a[i], wv[j], acc[i][j]);
            }
            __syncthreads();
        }
    }

    const int u0 = (n0 + tx * 8) >> 2;
#pragma unroll
    for (int i = 0; i < TM; i++) {
        int m = m0 + ty * TM + i;
        const float* xr = xg + (size_t)m * G4;
#pragma unroll
        for (int uu = 0; uu < 2; uu++) {
            int u = u0 + uu;
            float4 xv = *(const float4*)&xr[(size_t)u * 4];
            float pi = acc[i][uu * 4 + 0] + xv.x;
            float pf = acc[i][uu * 4 + 1] + xv.y;
            float pg = acc[i][uu * 4 + 2] + xv.z;
            float po = acc[i][uu * 4 + 3] + xv.w;
            float c  = zeroInit ? 0.f : Cin[(size_t)m * 1024 + u];
            float c2 = sigf(pf) * c + sigf(pi) * tanhf(pg);
            float h2 = sigf(po) * tanhf(c2);
            Hout[(size_t)m * 1024 + u] = h2;
            Cout[(size_t)m * 1024 + u] = c2;
        }
    }
}

// ---------------- host orchestration ----------------
extern "C" void kernel_launch(void* const* d_in, const int* in_sizes, int n_in,
                              void* d_out, int out_size) {
    (void)in_sizes; (void)n_in; (void)out_size;
    const float* inp   = (const float*)d_in[0];
    const float* Wih_r = (const float*)d_in[1];
    const float* Whh_r = (const float*)d_in[2];
    const float* bih_r = (const float*)d_in[3];
    const float* bhh_r = (const float*)d_in[4];
    const float* Wih_u = (const float*)d_in[5];
    const float* Whh_u = (const float*)d_in[6];
    const float* bih_u = (const float*)d_in[7];
    const float* bhh_u = (const float*)d_in[8];
    const float* Wc    = (const float*)d_in[9];
    const float* bc    = (const float*)d_in[10];
    float* out = (float*)d_out;

    __half *xT, *hu, *hn, *wihr, *wihu, *whhu, *wc;
    float *xg_r, *xg_u, *hs, *cs, *cu;
    cudaGetSymbolAddress((void**)&xT,   g_xT);
    cudaGetSymbolAddress((void**)&xg_r, g_xg_r);
    cudaGetSymbolAddress((void**)&xg_u, g_xg_u);
    cudaGetSymbolAddress((void**)&hs,   g_hs);
    cudaGetSymbolAddress((void**)&cs,   g_cs);
    cudaGetSymbolAddress((void**)&hu,   g_hu);
    cudaGetSymbolAddress((void**)&cu,   g_cu);
    cudaGetSymbolAddress((void**)&hn,   g_hn);
    cudaGetSymbolAddress((void**)&wihr, g_wihr);
    cudaGetSymbolAddress((void**)&wihu, g_wihu);
    cudaGetSymbolAddress((void**)&whhu, g_whhu);
    cudaGetSymbolAddress((void**)&wc,   g_wc);
    __half* hu0 = hu;
    __half* hu1 = hu + (size_t)SB * 1024;

    cudaFuncSetAttribute(k_mma_lstm, cudaFuncAttributeMaxDynamicSharedMemorySize, SMEM_LSTM);
    cudaFuncSetAttribute(k_mma_proj, cudaFuncAttributeMaxDynamicSharedMemorySize, SMEM_LIN);
    cudaFuncSetAttribute(k_cls,      cudaFuncAttributeMaxDynamicSharedMemorySize, SMEM_LIN);

    // 0) prep: all operands -> fp16 (+permute)
    k_prep_all<<<(PREP_TOT + 255) / 256, 256>>>(inp, Wih_r, Wih_u, Whh_u, Wc,
                                                xT, wihr, wihu, whhu, wc);

    // 1) both input projections in one launch (z selects r/u)
    {
        dim3 g(G4 / 128, SB / 128, 2);
        k_mma_proj<<<g, 256, SMEM_LIN>>>(xT,
                                         wihr, xg_r, bih_r, bhh_r,
                                         wihu, xg_u, bih_u, bhh_u);
    }

    // 2) rolling LSTM: 14 sequential FFMA steps (fp32-exact)
    for (int t = 0; t < S_; t++) {
        dim3 g(G4 / 128, B_ / 64);
        const float* hin = (t == 0) ? nullptr : hs + (size_t)(t - 1) * BH;
        const float* cin = (t == 0) ? nullptr : cs + (size_t)(t - 1) * BH;
        k_lstm_step<<<g, 256>>>(hin, Whh_r,
                                xg_r + (size_t)t * B_ * G4, cin,
                                hs + (size_t)t * BH, cs + (size_t)t * BH,
                                (t == 0) ? 1 : 0);
    }

    // 3) unroll h init (fp16 permuted); c: step 0 reads cs directly
    k_h2h<<<(SB * 32 + 255) / 256, 256>>>(hs, hu0);

    // 4) unroll LSTM: 15 steps; steps j>=2 carry classifier chunk for t=15-j
    for (int j = 0; j <= S_; j++) {
        int nact = (15 - j < 14) ? (15 - j) : 14;
        const __half* hin = (j & 1) ? hu1 : hu0;
        __half*       ho  = (j & 1) ? hu0 : hu1;
        const float*  cin = (j == 0) ? cs : cu;
        int final_t = S_ - j;
        int t_cls = (j >= 2) ? (15 - j) : -1;
        dim3 g(G4 / 128, nact * 2 + ((t_cls >= 0) ? 2 : 0));
        k_mma_lstm<<<g, 256, SMEM_LSTM>>>(hin, whhu, xg_u, cin, cu, ho, hn,
                                          final_t, nact * 2, t_cls, wc, bc, out);
    }

    // 5) final classifier chunk (instance t=0)
    {
        dim3 g(CLS_NB, 2);
        k_cls<<<g, 256, SMEM_LIN>>>(hn, wc, bc, out, 0);
    }
}

// round 14
// speedup vs baseline: 1.8860x; 1.2794x over previous
#include <cuda_runtime.h>
#include <cuda_fp16.h>
#include <math.h>
#include <stdint.h>

// ---------------- problem constants ----------------
#define B_ 256
#define S_ 14
#define C_ 2513
#define SB 3584          // S_*B_
#define BH 262144        // B_*H_
#define G4 4096          // 4*H_
#define CLS_NB 20        // ceil(2513/128)

// ---------------- fp16 mma GEMM config (128x128, 256 thr, occ 2) ----------
#define STAGE_H   4096
#define SLOT_H    (2 * STAGE_H)
#define NSTAGE    4
#define MAIN_H    (NSTAGE * SLOT_H)          // 32768 halves = 65536 B
#define SMEM_LSTM ((MAIN_H + 128 * 32) * 2)  // 73728 B
#define SMEM_LIN  (MAIN_H * 2 + 512)         // 66048 B

// ---------------- scratch (device globals) ----------------
__device__ __half g_xT [SB * 1024];
__device__ float  g_xg_r[(size_t)SB * G4];
__device__ float  g_xg_u[(size_t)SB * G4];
__device__ __half g_hu [2 * SB * 1024];
__device__ float  g_cu [SB * 1024];
__device__ __half g_hn [SB * 1024];
__device__ __half g_whhr[(size_t)G4 * 1024];
__device__ __half g_wihr[(size_t)G4 * 1024];
__device__ __half g_wihu[(size_t)G4 * 1024];
__device__ __half g_whhu[(size_t)G4 * 1024];
__device__ __half g_wc [(size_t)2560 * 1024];

__device__ __forceinline__ float sigf(float x) { return 1.0f / (1.0f + expf(-x)); }

// logical-k permutation within each 32-k block
__device__ __forceinline__ int perm_l(int p) {
    int b = (p >> 2) & 1, t = p >> 3, j = p & 3;
    return b * 16 + ((j < 2) ? (2 * t + j) : (2 * t + 8 + (j - 2)));
}
__device__ __forceinline__ int inv_l(int l) {
    int b = l >> 4, r = l & 15, hi = r >> 3, t = (r >> 1) & 3, e = r & 1;
    return t * 8 + b * 4 + hi * 2 + e;
}

// ---------------- low-level helpers ----------------
__device__ __forceinline__ uint32_t smaddr(const void* p) {
    uint32_t a;
    asm("{ .reg .u64 t; cvta.to.shared.u64 t, %1; cvt.u32.u64 %0, t; }" : "=r"(a) : "l"(p));
    return a;
}
__device__ __forceinline__ void cp16(uint32_t d, const void* s) {
    asm volatile("cp.async.cg.shared.global [%0], [%1], 16;" :: "r"(d), "l"(s));
}
__device__ __forceinline__ void cp16z(uint32_t d, const void* s, int sz) {
    asm volatile("cp.async.cg.shared.global [%0], [%1], 16, %2;" :: "r"(d), "l"(s), "r"(sz));
}
__device__ __forceinline__ void cpcommit() { asm volatile("cp.async.commit_group;"); }
template <int N>
__device__ __forceinline__ void cpwait() { asm volatile("cp.async.wait_group %0;" :: "n"(N)); }
__device__ __forceinline__ void mma16(float* d, const uint32_t* a, const uint32_t* b) {
    asm volatile(
        "mma.sync.aligned.m16n8k16.row.col.f32.f16.f16.f32 "
        "{%0,%1,%2,%3},{%4,%5,%6,%7},{%8,%9},{%0,%1,%2,%3};"
        : "+f"(d[0]), "+f"(d[1]), "+f"(d[2]), "+f"(d[3])
        : "r"(a[0]), "r"(a[1]), "r"(a[2]), "r"(a[3]), "r"(b[0]), "r"(b[1]));
}

// ---------------- stage issue (256 threads, 128x32 A + 128x32 B) ----------
template <int EDGE>
__device__ __forceinline__ void stage_issue(
    __half* sm, int slot, const __half* __restrict__ A, const __half* __restrict__ W,
    int m0, int n0, int kt, int Nb, int tid)
{
    __half* dA = sm + slot * SLOT_H;
    __half* dB = dA + STAGE_H;
    const __half* Ap = A + (size_t)m0 * 1024 + kt * 32;
    const __half* Wp = W + (size_t)n0 * 1024 + kt * 32;
#pragma unroll
    for (int i = 0; i < 2; i++) {
        int c = tid + (i << 8);
        int row = c >> 2, c16 = c & 3;
        cp16(smaddr(dA + row * 32 + c16 * 8), Ap + (size_t)row * 1024 + c16 * 8);
        if (EDGE) {
            int ok = (n0 + row < Nb);
            cp16z(smaddr(dB + row * 32 + c16 * 8),
                  Wp + (size_t)(ok ? row : 0) * 1024 + c16 * 8, ok ? 16 : 0);
        } else {
            cp16(smaddr(dB + row * 32 + c16 * 8), Wp + (size_t)row * 1024 + c16 * 8);
        }
    }
    cpcommit();
}

// ---------------- stage compute: 64x32 warp tile, 32 MMAs ------------------
__device__ __forceinline__ void stage_compute(
    const __half* sm, int slot, int wm, int wn, int g, int tig, float acc[4][4][4])
{
    const __half* bA = sm + slot * SLOT_H + (size_t)(wm * 64 + g) * 32 + tig * 8;
    const __half* bB = sm + slot * SLOT_H + STAGE_H + (size_t)(wn * 32 + g) * 32 + tig * 8;
    uint4 bq[4];
#pragma unroll
    for (int ni = 0; ni < 4; ni++)
        bq[ni] = *(const uint4*)(bB + ni * 8 * 32);
#pragma unroll
    for (int mp = 0; mp < 2; mp++) {
        const int m0i = mp * 2, m1i = mp * 2 + 1;
        uint4 alo0 = *(const uint4*)(bA + m0i * 16 * 32);
        uint4 ahi0 = *(const uint4*)(bA + (m0i * 16 + 8) * 32);
        uint4 alo1 = *(const uint4*)(bA + m1i * 16 * 32);
        uint4 ahi1 = *(const uint4*)(bA + (m1i * 16 + 8) * 32);
        uint32_t a00[4] = {alo0.x, ahi0.x, alo0.y, ahi0.y};
        uint32_t a01[4] = {alo0.z, ahi0.z, alo0.w, ahi0.w};
        uint32_t a10[4] = {alo1.x, ahi1.x, alo1.y, ahi1.y};
        uint32_t a11[4] = {alo1.z, ahi1.z, alo1.w, ahi1.w};
#pragma unroll
        for (int ni = 0; ni < 4; ni++) {
            uint32_t bf0[2] = {bq[ni].x, bq[ni].y};
            mma16(acc[m0i][ni], a00, bf0);
        }
#pragma unroll
        for (int ni = 0; ni < 4; ni++) {
            uint32_t bf0[2] = {bq[ni].x, bq[ni].y};
            mma16(acc[m1i][ni], a10, bf0);
        }
#pragma unroll
        for (int ni = 0; ni < 4; ni++) {
            uint32_t bf1[2] = {bq[ni].z, bq[ni].w};
            mma16(acc[m0i][ni], a01, bf1);
        }
#pragma unroll
        for (int ni = 0; ni < 4; ni++) {
            uint32_t bf1[2] = {bq[ni].z, bq[ni].w};
            mma16(acc[m1i][ni], a11, bf1);
        }
    }
}

// ---------------- full K=1024 mainloop (4-stage, 1 sync/iter) --------------
template <int EDGE>
__device__ __forceinline__ void run_mainloop(
    __half* sm, const __half* __restrict__ A, const __half* __restrict__ W,
    int m0, int n0, int Nb, float acc[4][4][4],
    int tid, int wm, int wn, int g, int tig)
{
    stage_issue<EDGE>(sm, 0, A, W, m0, n0, 0, Nb, tid);
    stage_issue<EDGE>(sm, 1, A, W, m0, n0, 1, Nb, tid);
    stage_issue<EDGE>(sm, 2, A, W, m0, n0, 2, Nb, tid);
#pragma unroll 1
    for (int kt = 0; kt < 32; kt++) {
        int slot = kt & 3;
        if (kt < 30)       cpwait<2>();
        else if (kt == 30) cpwait<1>();
        else               cpwait<0>();
        __syncthreads();
        if (kt + 3 < 32) stage_issue<EDGE>(sm, (kt + 3) & 3, A, W, m0, n0, kt + 3, Nb, tid);
        stage_compute(sm, slot, wm, wn, g, tig, acc);
    }
}

// ---------------- classifier tile (device fn) -------------------------------
__device__ __forceinline__ void cls_tile(
    __half* sm, const __half* __restrict__ hn, const __half* __restrict__ wc,
    const float* __restrict__ bc, float* __restrict__ out,
    int m0, int n0, int tid, int wm, int wn, int g, int tig)
{
    float* biasS = (float*)(sm + MAIN_H);
    if (tid < 128) {
        int np = n0 + tid;
        biasS[tid] = (np < C_) ? bc[np] : 0.f;
    }
    float acc[4][4][4];
#pragma unroll
    for (int a = 0; a < 4; a++)
#pragma unroll
        for (int b = 0; b < 4; b++)
#pragma unroll
            for (int c = 0; c < 4; c++) acc[a][b][c] = 0.f;

    run_mainloop<1>(sm, hn, wc, m0, n0, C_, acc, tid, wm, wn, g, tig);

#pragma unroll
    for (int mi = 0; mi < 4; mi++) {
        const int R0 = m0 + wm * 64 + mi * 16;
#pragma unroll
        for (int ni = 0; ni < 4; ni++) {
            const int v = n0 + wn * 32 + ni * 8 + 2 * tig;
            const float bA0 = biasS[v - n0], bA1 = biasS[v - n0 + 1];
            const int r1 = R0 + g, r2 = R0 + g + 8;
            int or1 = (r1 & 255) * S_ + (r1 >> 8);
            int or2 = (r2 & 255) * S_ + (r2 >> 8);
            if (v < C_) {
                out[(size_t)or1 * C_ + v] = acc[mi][ni][0] + bA0;
                out[(size_t)or2 * C_ + v] = acc[mi][ni][2] + bA0;
            }
            if (v + 1 < C_) {
                out[(size_t)or1 * C_ + v + 1] = acc[mi][ni][1] + bA1;
                out[(size_t)or2 * C_ + v + 1] = acc[mi][ni][3] + bA1;
            }
        }
    }
}

// ---------------- fused LSTM step (rolling AND unroll) + cls piggyback -----
// zeroInit: h=0, c=0 (rolling t=0) -> skip mainloop entirely.
__global__ void __launch_bounds__(256, 2) k_mma_lstm(
    const __half* __restrict__ Hin, const __half* __restrict__ Whh,
    const float* __restrict__ xg,
    const float* __restrict__ Cin, float* __restrict__ Cout,
    __half* __restrict__ Hout, __half* __restrict__ hn, int final_t,
    int nact2, int t_cls, int zeroInit,
    const __half* __restrict__ wc, const float* __restrict__ bc,
    float* __restrict__ out)
{
    extern __shared__ __half sm[];
    __half* hsm = sm + MAIN_H;
    const int tid = threadIdx.x, lane = tid & 31, wid = tid >> 5;
    const int wm = wid & 1, wn = wid >> 1, g = lane >> 2, tig = lane & 3;

    if ((int)blockIdx.y >= nact2) {
        if (blockIdx.x >= CLS_NB) return;
        int mb = t_cls * 2 + ((int)blockIdx.y - nact2);
        cls_tile(sm, hn, wc, bc, out, mb * 128, blockIdx.x * 128,
                 tid, wm, wn, g, tig);
        return;
    }

    const int m0 = blockIdx.y * 128, n0 = blockIdx.x * 128;

    float acc[4][4][4];
#pragma unroll
    for (int a = 0; a < 4; a++)
#pragma unroll
        for (int b = 0; b < 4; b++)
#pragma unroll
            for (int c = 0; c < 4; c++) acc[a][b][c] = 0.f;

    if (!zeroInit)
        run_mainloop<0>(sm, Hin, Whh, m0, n0, 0x7fffffff, acc, tid, wm, wn, g, tig);

#pragma unroll
    for (int mi = 0; mi < 4; mi++) {
        const int R0 = m0 + wm * 64 + mi * 16;
#pragma unroll
        for (int ni = 0; ni < 4; ni++) {
            const int V0 = n0 + wn * 32 + ni * 8;
            float c0 = acc[mi][ni][0], c1 = acc[mi][ni][1];
            float c2 = acc[mi][ni][2], c3 = acc[mi][ni][3];
            int p = tig & 1;
            float x = p ? c0 : c2, y = p ? c1 : c3;
            float sx = __shfl_xor_sync(0xffffffffu, x, 1);
            float sy = __shfl_xor_sync(0xffffffffu, y, 1);
            float pi, pf, pg, po; int row;
            if (!p) { pi = c0; pf = c1; pg = sx; po = sy; row = R0 + g; }
            else    { pi = sx; pf = sy; pg = c2; po = c3; row = R0 + g + 8; }
            int u = (V0 >> 2) + (tig >> 1);
            float4 xv = *(const float4*)(xg + (size_t)row * G4 + u * 4);
            float ci = zeroInit ? 0.f : Cin[(size_t)row * 1024 + u];
            float cn = sigf(pf + xv.y) * ci + sigf(pi + xv.x) * tanhf(pg + xv.z);
            float hv = sigf(po + xv.w) * tanhf(cn);
            Cout[(size_t)row * 1024 + u] = cn;
            int ul = u - (n0 >> 2);
            hsm[(row - m0) * 32 + inv_l(ul)] = __float2half_rn(hv);
        }
    }
    __syncthreads();
    {
        int r = tid >> 1, seg = tid & 1;
        int m = m0 + r;
        const uint4* src = (const uint4*)(hsm + r * 32 + seg * 16);
        uint4 a = src[0], b = src[1];
        __half* gd = Hout + (size_t)m * 1024 + (n0 >> 2) + seg * 16;
        ((uint4*)gd)[0] = a; ((uint4*)gd)[1] = b;
        if ((m >> 8) == final_t) {
            __half* fd = hn + (size_t)m * 1024 + (n0 >> 2) + seg * 16;
            ((uint4*)fd)[0] = a; ((uint4*)fd)[1] = b;
        }
    }
}

// ---------------- standalone classifier chunk (instance t) -----------------
__global__ void __launch_bounds__(256, 2) k_cls(
    const __half* __restrict__ hn, const __half* __restrict__ wc,
    const float* __restrict__ bc, float* __restrict__ out, int t)
{
    extern __shared__ __half sm[];
    const int tid = threadIdx.x, lane = tid & 31, wid = tid >> 5;
    const int wm = wid & 1, wn = wid >> 1, g = lane >> 2, tig = lane & 3;
    int mb = t * 2 + blockIdx.y;
    cls_tile(sm, hn, wc, bc, out, mb * 128, blockIdx.x * 128, tid, wm, wn, g, tig);
}

// ---------------- merged projections (blockIdx.z selects r/u set) ----------
__global__ void __launch_bounds__(256, 2) k_mma_proj(
    const __half* __restrict__ A,
    const __half* __restrict__ W0, float* __restrict__ O0,
    const float* __restrict__ b00, const float* __restrict__ b01,
    const __half* __restrict__ W1, float* __restrict__ O1,
    const float* __restrict__ b10, const float* __restrict__ b11)
{
    extern __shared__ __half sm[];
    float* biasS = (float*)(sm + MAIN_H);
    const int tid = threadIdx.x, lane = tid & 31, wid = tid >> 5;
    const int wm = wid & 1, wn = wid >> 1, g = lane >> 2, tig = lane & 3;
    const int m0 = blockIdx.y * 128, n0 = blockIdx.x * 128;
    const int sel = blockIdx.z;
    const __half* W = sel ? W1 : W0;
    float* Out = sel ? O1 : O0;
    const float* b0 = sel ? b10 : b00;
    const float* b1 = sel ? b11 : b01;

    if (tid < 128) {
        int np = n0 + tid;
        int wr = ((np & 3) << 10) | (np >> 2);
        biasS[tid] = b0[wr] + b1[wr];
    }

    float acc[4][4][4];
#pragma unroll
    for (int a = 0; a < 4; a++)
#pragma unroll
        for (int b = 0; b < 4; b++)
#pragma unroll
            for (int c = 0; c < 4; c++) acc[a][b][c] = 0.f;

    run_mainloop<0>(sm, A, W, m0, n0, 0x7fffffff, acc, tid, wm, wn, g, tig);

#pragma unroll
    for (int mi = 0; mi < 4; mi++) {
        const int R0 = m0 + wm * 64 + mi * 16;
#pragma unroll
        for (int ni = 0; ni < 4; ni++) {
            const int v = n0 + wn * 32 + ni * 8 + 2 * tig;
            const float bA0 = biasS[v - n0], bA1 = biasS[v - n0 + 1];
            const int r1 = R0 + g, r2 = R0 + g + 8;
            float2 s1 = make_float2(acc[mi][ni][0] + bA0, acc[mi][ni][1] + bA1);
            float2 s2 = make_float2(acc[mi][ni][2] + bA0, acc[mi][ni][3] + bA1);
            *(float2*)(Out + (size_t)r1 * G4 + v) = s1;
            *(float2*)(Out + (size_t)r2 * G4 + v) = s2;
        }
    }
}

// ---------------- merged prep kernel (fp32 -> fp16 + k-permute) ------------
#define PREP_XT   (SB * 32)
#define PREP_W    (G4 * 32)
#define PREP_WC   (C_ * 32)
#define PREP_TOT  (PREP_XT + 4 * PREP_W + PREP_WC)

__global__ void k_prep_all(
    const float* __restrict__ inp,
    const float* __restrict__ Whh_r, const float* __restrict__ Wih_r,
    const float* __restrict__ Wih_u, const float* __restrict__ Whh_u,
    const float* __restrict__ Wc,
    __half* __restrict__ xT, __half* __restrict__ whhr, __half* __restrict__ wihr,
    __half* __restrict__ wihu, __half* __restrict__ whhu, __half* __restrict__ wc)
{
    int idx = blockIdx.x * blockDim.x + threadIdx.x;
    if (idx >= PREP_TOT) return;
    const float* src;
    __half* dstbase;
    int r, b32;
    if (idx < PREP_XT) {
        r = idx >> 5; b32 = idx & 31;
        int b = r % B_, s = r / B_;
        src = inp + (size_t)(b * S_ + s) * 1024 + b32 * 32;
        dstbase = xT;
    } else {
        int t = idx - PREP_XT;
        int seg = t / PREP_W;
        if (seg < 4) {
            int u = t - seg * PREP_W;
            r = u >> 5; b32 = u & 31;
            int wr = ((r & 3) << 10) | (r >> 2);
            const float* W = (seg == 0) ? Whh_r : (seg == 1) ? Wih_r
                            : (seg == 2) ? Wih_u : Whh_u;
            src = W + (size_t)wr * 1024 + b32 * 32;
            dstbase = (seg == 0) ? whhr : (seg == 1) ? wihr
                    : (seg == 2) ? wihu : whhu;
        } else {
            int u = t - 4 * PREP_W;
            r = u >> 5; b32 = u & 31;
            src = Wc + (size_t)r * 1024 + b32 * 32;
            dstbase = wc;
        }
    }
    float v[32];
#pragma unroll
    for (int i = 0; i < 8; i++) *(float4*)&v[i * 4] = *(const float4*)(src + i * 4);
    __half h[32];
#pragma unroll
    for (int p = 0; p < 32; p++) h[p] = __float2half_rn(v[perm_l(p)]);
    uint4* dst = (uint4*)(dstbase + (size_t)r * 1024 + b32 * 32);
#pragma unroll
    for (int i = 0; i < 4; i++) dst[i] = ((const uint4*)h)[i];
}

// ---------------- host orchestration ----------------
extern "C" void kernel_launch(void* const* d_in, const int* in_sizes, int n_in,
                              void* d_out, int out_size) {
    (void)in_sizes; (void)n_in; (void)out_size;
    const float* inp   = (const float*)d_in[0];
    const float* Wih_r = (const float*)d_in[1];
    const float* Whh_r = (const float*)d_in[2];
    const float* bih_r = (const float*)d_in[3];
    const float* bhh_r = (const float*)d_in[4];
    const float* Wih_u = (const float*)d_in[5];
    const float* Whh_u = (const float*)d_in[6];
    const float* bih_u = (const float*)d_in[7];
    const float* bhh_u = (const float*)d_in[8];
    const float* Wc    = (const float*)d_in[9];
    const float* bc    = (const float*)d_in[10];
    float* out = (float*)d_out;

    __half *xT, *hu, *hn, *whhr, *wihr, *wihu, *whhu, *wc;
    float *xg_r, *xg_u, *cu;
    cudaGetSymbolAddress((void**)&xT,   g_xT);
    cudaGetSymbolAddress((void**)&xg_r, g_xg_r);
    cudaGetSymbolAddress((void**)&xg_u, g_xg_u);
    cudaGetSymbolAddress((void**)&hu,   g_hu);
    cudaGetSymbolAddress((void**)&cu,   g_cu);
    cudaGetSymbolAddress((void**)&hn,   g_hn);
    cudaGetSymbolAddress((void**)&whhr, g_whhr);
    cudaGetSymbolAddress((void**)&wihr, g_wihr);
    cudaGetSymbolAddress((void**)&wihu, g_wihu);
    cudaGetSymbolAddress((void**)&whhu, g_whhu);
    cudaGetSymbolAddress((void**)&wc,   g_wc);
    __half* hu0 = hu;
    __half* hu1 = hu + (size_t)SB * 1024;

    cudaFuncSetAttribute(k_mma_lstm, cudaFuncAttributeMaxDynamicSharedMemorySize, SMEM_LSTM);
    cudaFuncSetAttribute(k_mma_proj, cudaFuncAttributeMaxDynamicSharedMemorySize, SMEM_LIN);
    cudaFuncSetAttribute(k_cls,      cudaFuncAttributeMaxDynamicSharedMemorySize, SMEM_LIN);

    // 0) prep: all operands -> fp16 (+permute); now includes Whh_r
    k_prep_all<<<(PREP_TOT + 255) / 256, 256>>>(inp, Whh_r, Wih_r, Wih_u, Whh_u, Wc,
                                                xT, whhr, wihr, wihu, whhu, wc);

    // 1) both input projections in one launch (z selects r/u)
    {
        dim3 g(G4 / 128, SB / 128, 2);
        k_mma_proj<<<g, 256, SMEM_LIN>>>(xT,
                                         wihr, xg_r, bih_r, bhh_r,
                                         wihu, xg_u, bih_u, bhh_u);
    }

    // 2) rolling LSTM: 14 fp16-mma steps (M=256); step t writes h into hu0
    //    slice t and c into cu slice t — these ARE the unroll initial states.
    for (int t = 0; t < S_; t++) {
        dim3 g(G4 / 128, 2);
        const __half* hin = hu0 + (size_t)(t - 1) * BH;   // unused when t==0
        const float*  cin = cu + (size_t)(t - 1) * BH;
        k_mma_lstm<<<g, 256, SMEM_LSTM>>>(
            (t == 0) ? hu0 : hin, whhr,
            xg_r + (size_t)t * B_ * G4,
            (t == 0) ? cu : cin, cu + (size_t)t * BH,
            hu0 + (size_t)t * BH, hn, /*final_t=*/-1,
            /*nact2=*/2, /*t_cls=*/-1, /*zeroInit=*/(t == 0) ? 1 : 0,
            wc, bc, out);
    }

    // 3) unroll LSTM: 15 steps; steps j>=2 carry classifier chunk for t=15-j
    for (int j = 0; j <= S_; j++) {
        int nact = (15 - j < 14) ? (15 - j) : 14;
        const __half* hin = (j & 1) ? hu1 : hu0;
        __half*       ho  = (j & 1) ? hu0 : hu1;
        int final_t = S_ - j;
        int t_cls = (j >= 2) ? (15 - j) : -1;
        dim3 g(G4 / 128, nact * 2 + ((t_cls >= 0) ? 2 : 0));
        k_mma_lstm<<<g, 256, SMEM_LSTM>>>(hin, whhu, xg_u, cu, cu, ho, hn,
                                          final_t, nact * 2, t_cls, 0,
                                          wc, bc, out);
    }

    // 4) final classifier chunk (instance t=0)
    {
        dim3 g(CLS_NB, 2);
        k_cls<<<g, 256, SMEM_LIN>>>(hn, wc, bc, out, 0);
    }
}

// round 16
// speedup vs baseline: 2.2124x; 1.1731x over previous
#include <cuda_runtime.h>
#include <cuda_fp16.h>
#include <math.h>
#include <stdint.h>

// ---------------- problem constants ----------------
#define B_ 256
#define S_ 14
#define C_ 2513
#define SB 3584          // S_*B_
#define BH 262144        // B_*H_
#define G4 4096          // 4*H_
#define CLS_NB 20        // ceil(2513/128)
#define PROJ_TILES 1792  // 896 xg_r + 896 xg_u
#define PRELAUNCH 608    // proj tiles before rolling
#define RIDE 88          // proj tiles per rolling launch

// ---------------- fp16 mma GEMM config (128x128, 256 thr, occ 2) ----------
#define STAGE_H   4096
#define SLOT_H    (2 * STAGE_H)
#define NSTAGE    4
#define MAIN_H    (NSTAGE * SLOT_H)          // 32768 halves = 65536 B
#define SMEM_LSTM ((MAIN_H + 128 * 32) * 2)  // 73728 B
#define SMEM_LIN  (MAIN_H * 2 + 512)         // 66048 B

// ---------------- scratch (device globals) ----------------
__device__ __half g_xT [SB * 1024];
__device__ float  g_xg_r[(size_t)SB * G4];
__device__ float  g_xg_u[(size_t)SB * G4];
__device__ __half g_hu [2 * SB * 1024];
__device__ float  g_cu [SB * 1024];
__device__ __half g_hn [SB * 1024];
__device__ __half g_whhr[(size_t)G4 * 1024];
__device__ __half g_wihr[(size_t)G4 * 1024];
__device__ __half g_wihu[(size_t)G4 * 1024];
__device__ __half g_whhu[(size_t)G4 * 1024];
__device__ __half g_wc [(size_t)2560 * 1024];

__device__ __forceinline__ float sigf(float x) { return 1.0f / (1.0f + expf(-x)); }

// logical-k permutation within each 32-k block
__device__ __forceinline__ int perm_l(int p) {
    int b = (p >> 2) & 1, t = p >> 3, j = p & 3;
    return b * 16 + ((j < 2) ? (2 * t + j) : (2 * t + 8 + (j - 2)));
}
__device__ __forceinline__ int inv_l(int l) {
    int b = l >> 4, r = l & 15, hi = r >> 3, t = (r >> 1) & 3, e = r & 1;
    return t * 8 + b * 4 + hi * 2 + e;
}

// ---------------- low-level helpers ----------------
__device__ __forceinline__ uint32_t smaddr(const void* p) {
    uint32_t a;
    asm("{ .reg .u64 t; cvta.to.shared.u64 t, %1; cvt.u32.u64 %0, t; }" : "=r"(a) : "l"(p));
    return a;
}
__device__ __forceinline__ void cp16(uint32_t d, const void* s) {
    asm volatile("cp.async.cg.shared.global [%0], [%1], 16;" :: "r"(d), "l"(s));
}
__device__ __forceinline__ void cp16z(uint32_t d, const void* s, int sz) {
    asm volatile("cp.async.cg.shared.global [%0], [%1], 16, %2;" :: "r"(d), "l"(s), "r"(sz));
}
__device__ __forceinline__ void cpcommit() { asm volatile("cp.async.commit_group;"); }
template <int N>
__device__ __forceinline__ void cpwait() { asm volatile("cp.async.wait_group %0;" :: "n"(N)); }
__device__ __forceinline__ void mma16(float* d, const uint32_t* a, const uint32_t* b) {
    asm volatile(
        "mma.sync.aligned.m16n8k16.row.col.f32.f16.f16.f32 "
        "{%0,%1,%2,%3},{%4,%5,%6,%7},{%8,%9},{%0,%1,%2,%3};"
        : "+f"(d[0]), "+f"(d[1]), "+f"(d[2]), "+f"(d[3])
        : "r"(a[0]), "r"(a[1]), "r"(a[2]), "r"(a[3]), "r"(b[0]), "r"(b[1]));
}

// ---------------- stage issue (256 threads, 128x32 A + 128x32 B) ----------
template <int EDGE>
__device__ __forceinline__ void stage_issue(
    __half* sm, int slot, const __half* __restrict__ A, const __half* __restrict__ W,
    int m0, int n0, int kt, int Nb, int tid)
{
    __half* dA = sm + slot * SLOT_H;
    __half* dB = dA + STAGE_H;
    const __half* Ap = A + (size_t)m0 * 1024 + kt * 32;
    const __half* Wp = W + (size_t)n0 * 1024 + kt * 32;
#pragma unroll
    for (int i = 0; i < 2; i++) {
        int c = tid + (i << 8);
        int row = c >> 2, c16 = c & 3;
        cp16(smaddr(dA + row * 32 + c16 * 8), Ap + (size_t)row * 1024 + c16 * 8);
        if (EDGE) {
            int ok = (n0 + row < Nb);
            cp16z(smaddr(dB + row * 32 + c16 * 8),
                  Wp + (size_t)(ok ? row : 0) * 1024 + c16 * 8, ok ? 16 : 0);
        } else {
            cp16(smaddr(dB + row * 32 + c16 * 8), Wp + (size_t)row * 1024 + c16 * 8);
        }
    }
    cpcommit();
}

// ---------------- stage compute: 64x32 warp tile, 32 MMAs ------------------
__device__ __forceinline__ void stage_compute(
    const __half* sm, int slot, int wm, int wn, int g, int tig, float acc[4][4][4])
{
    const __half* bA = sm + slot * SLOT_H + (size_t)(wm * 64 + g) * 32 + tig * 8;
    const __half* bB = sm + slot * SLOT_H + STAGE_H + (size_t)(wn * 32 + g) * 32 + tig * 8;
    uint4 bq[4];
#pragma unroll
    for (int ni = 0; ni < 4; ni++)
        bq[ni] = *(const uint4*)(bB + ni * 8 * 32);
#pragma unroll
    for (int mp = 0; mp < 2; mp++) {
        const int m0i = mp * 2, m1i = mp * 2 + 1;
        uint4 alo0 = *(const uint4*)(bA + m0i * 16 * 32);
        uint4 ahi0 = *(const uint4*)(bA + (m0i * 16 + 8) * 32);
        uint4 alo1 = *(const uint4*)(bA + m1i * 16 * 32);
        uint4 ahi1 = *(const uint4*)(bA + (m1i * 16 + 8) * 32);
        uint32_t a00[4] = {alo0.x, ahi0.x, alo0.y, ahi0.y};
        uint32_t a01[4] = {alo0.z, ahi0.z, alo0.w, ahi0.w};
        uint32_t a10[4] = {alo1.x, ahi1.x, alo1.y, ahi1.y};
        uint32_t a11[4] = {alo1.z, ahi1.z, alo1.w, ahi1.w};
#pragma unroll
        for (int ni = 0; ni < 4; ni++) {
            uint32_t bf0[2] = {bq[ni].x, bq[ni].y};
            mma16(acc[m0i][ni], a00, bf0);
        }
#pragma unroll
        for (int ni = 0; ni < 4; ni++) {
            uint32_t bf0[2] = {bq[ni].x, bq[ni].y};
            mma16(acc[m1i][ni], a10, bf0);
        }
#pragma unroll
        for (int ni = 0; ni < 4; ni++) {
            uint32_t bf1[2] = {bq[ni].z, bq[ni].w};
            mma16(acc[m0i][ni], a01, bf1);
        }
#pragma unroll
        for (int ni = 0; ni < 4; ni++) {
            uint32_t bf1[2] = {bq[ni].z, bq[ni].w};
            mma16(acc[m1i][ni], a11, bf1);
        }
    }
}

// ---------------- full K=1024 mainloop (4-stage, 1 sync/iter) --------------
template <int EDGE>
__device__ __forceinline__ void run_mainloop(
    __half* sm, const __half* __restrict__ A, const __half* __restrict__ W,
    int m0, int n0, int Nb, float acc[4][4][4],
    int tid, int wm, int wn, int g, int tig)
{
    stage_issue<EDGE>(sm, 0, A, W, m0, n0, 0, Nb, tid);
    stage_issue<EDGE>(sm, 1, A, W, m0, n0, 1, Nb, tid);
    stage_issue<EDGE>(sm, 2, A, W, m0, n0, 2, Nb, tid);
#pragma unroll 1
    for (int kt = 0; kt < 32; kt++) {
        int slot = kt & 3;
        if (kt < 30)       cpwait<2>();
        else if (kt == 30) cpwait<1>();
        else               cpwait<0>();
        __syncthreads();
        if (kt + 3 < 32) stage_issue<EDGE>(sm, (kt + 3) & 3, A, W, m0, n0, kt + 3, Nb, tid);
        stage_compute(sm, slot, wm, wn, g, tig, acc);
    }
}

// ---------------- projection tile (device fn) ------------------------------
__device__ __forceinline__ void proj_tile(
    __half* sm, const __half* __restrict__ A, const __half* __restrict__ W,
    float* __restrict__ Out, const float* __restrict__ b0,
    const float* __restrict__ b1, int m0, int n0,
    int tid, int wm, int wn, int g, int tig)
{
    float* biasS = (float*)(sm + MAIN_H);
    if (tid < 128) {
        int np = n0 + tid;
        int wr = ((np & 3) << 10) | (np >> 2);
        biasS[tid] = b0[wr] + b1[wr];
    }
    float acc[4][4][4];
#pragma unroll
    for (int a = 0; a < 4; a++)
#pragma unroll
        for (int b = 0; b < 4; b++)
#pragma unroll
            for (int c = 0; c < 4; c++) acc[a][b][c] = 0.f;

    run_mainloop<0>(sm, A, W, m0, n0, 0x7fffffff, acc, tid, wm, wn, g, tig);

#pragma unroll
    for (int mi = 0; mi < 4; mi++) {
        const int R0 = m0 + wm * 64 + mi * 16;
#pragma unroll
        for (int ni = 0; ni < 4; ni++) {
            const int v = n0 + wn * 32 + ni * 8 + 2 * tig;
            const float bA0 = biasS[v - n0], bA1 = biasS[v - n0 + 1];
            const int r1 = R0 + g, r2 = R0 + g + 8;
            float2 s1 = make_float2(acc[mi][ni][0] + bA0, acc[mi][ni][1] + bA1);
            float2 s2 = make_float2(acc[mi][ni][2] + bA0, acc[mi][ni][3] + bA1);
            *(float2*)(Out + (size_t)r1 * G4 + v) = s1;
            *(float2*)(Out + (size_t)r2 * G4 + v) = s2;
        }
    }
}

// ---------------- proj queue decode: q in [0, PROJ_TILES) ------------------
// q < 896: xg_r, slice-major (slice t occupies m-blocks 2t, 2t+1).
// q >= 896: xg_u, m-major.
__device__ __forceinline__ void projq_tile(
    __half* sm, int q,
    const __half* __restrict__ xT,
    const __half* __restrict__ wihr, const __half* __restrict__ wihu,
    float* __restrict__ xg_r, float* __restrict__ xg_u,
    const float* __restrict__ bihr, const float* __restrict__ bhhr,
    const float* __restrict__ bihu, const float* __restrict__ bhhu,
    int tid, int wm, int wn, int g, int tig)
{
    if (q >= PROJ_TILES) return;
    const __half* W; float* O; const float *b0, *b1; int m0, n0;
    if (q < 896) {
        int slice = q >> 6, w = q & 63;
        m0 = (slice * 2 + (w >> 5)) * 128;
        n0 = (w & 31) * 128;
        W = wihr; O = xg_r; b0 = bihr; b1 = bhhr;
    } else {
        int p = q - 896;
        m0 = (p >> 5) * 128;
        n0 = (p & 31) * 128;
        W = wihu; O = xg_u; b0 = bihu; b1 = bhhu;
    }
    proj_tile(sm, xT, W, O, b0, b1, m0, n0, tid, wm, wn, g, tig);
}

// ---------------- proj pre-launch kernel ------------------------------------
__global__ void __launch_bounds__(256, 2) k_projq(
    const __half* __restrict__ xT,
    const __half* __restrict__ wihr, const __half* __restrict__ wihu,
    float* __restrict__ xg_r, float* __restrict__ xg_u,
    const float* __restrict__ bihr, const float* __restrict__ bhhr,
    const float* __restrict__ bihu, const float* __restrict__ bhhu)
{
    extern __shared__ __half sm[];
    const int tid = threadIdx.x, lane = tid & 31, wid = tid >> 5;
    const int wm = wid & 1, wn = wid >> 1, g = lane >> 2, tig = lane & 3;
    projq_tile(sm, blockIdx.x, xT, wihr, wihu, xg_r, xg_u,
               bihr, bhhr, bihu, bhhu, tid, wm, wn, g, tig);
}

// ---------------- rolling step kernel (64 LSTM tiles + 88 proj riders) -----
__global__ void __launch_bounds__(256, 2) k_roll(
    const __half* __restrict__ Hin, const __half* __restrict__ Whh,
    const float* __restrict__ xg,
    const float* __restrict__ Cin, float* __restrict__ Cout,
    __half* __restrict__ Hout, int zeroInit, int projBase,
    const __half* __restrict__ xT,
    const __half* __restrict__ wihr, const __half* __restrict__ wihu,
    float* __restrict__ xg_r, float* __restrict__ xg_u,
    const float* __restrict__ bihr, const float* __restrict__ bhhr,
    const float* __restrict__ bihu, const float* __restrict__ bhhu)
{
    extern __shared__ __half sm[];
    __half* hsm = sm + MAIN_H;
    const int tid = threadIdx.x, lane = tid & 31, wid = tid >> 5;
    const int wm = wid & 1, wn = wid >> 1, g = lane >> 2, tig = lane & 3;
    const int x = blockIdx.x;

    if (x >= 64) {
        projq_tile(sm, projBase + (x - 64), xT, wihr, wihu, xg_r, xg_u,
                   bihr, bhhr, bihu, bhhu, tid, wm, wn, g, tig);
        return;
    }

    const int m0 = (x >> 5) * 128, n0 = (x & 31) * 128;

    float acc[4][4][4];
#pragma unroll
    for (int a = 0; a < 4; a++)
#pragma unroll
        for (int b = 0; b < 4; b++)
#pragma unroll
            for (int c = 0; c < 4; c++) acc[a][b][c] = 0.f;

    if (!zeroInit)
        run_mainloop<0>(sm, Hin, Whh, m0, n0, 0x7fffffff, acc, tid, wm, wn, g, tig);

#pragma unroll
    for (int mi = 0; mi < 4; mi++) {
        const int R0 = m0 + wm * 64 + mi * 16;
#pragma unroll
        for (int ni = 0; ni < 4; ni++) {
            const int V0 = n0 + wn * 32 + ni * 8;
            float c0 = acc[mi][ni][0], c1 = acc[mi][ni][1];
            float c2 = acc[mi][ni][2], c3 = acc[mi][ni][3];
            int p = tig & 1;
            float xa = p ? c0 : c2, ya = p ? c1 : c3;
            float sx = __shfl_xor_sync(0xffffffffu, xa, 1);
            float sy = __shfl_xor_sync(0xffffffffu, ya, 1);
            float pi, pf, pg, po; int row;
            if (!p) { pi = c0; pf = c1; pg = sx; po = sy; row = R0 + g; }
            else    { pi = sx; pf = sy; pg = c2; po = c3; row = R0 + g + 8; }
            int u = (V0 >> 2) + (tig >> 1);
            float4 xv = *(const float4*)(xg + (size_t)row * G4 + u * 4);
            float ci = zeroInit ? 0.f : Cin[(size_t)row * 1024 + u];
            float cn = sigf(pf + xv.y) * ci + sigf(pi + xv.x) * tanhf(pg + xv.z);
            float hv = sigf(po + xv.w) * tanhf(cn);
            Cout[(size_t)row * 1024 + u] = cn;
            int ul = u - (n0 >> 2);
            hsm[(row - m0) * 32 + inv_l(ul)] = __float2half_rn(hv);
        }
    }
    __syncthreads();
    {
        int r = tid >> 1, seg = tid & 1;
        int m = m0 + r;
        const uint4* src = (const uint4*)(hsm + r * 32 + seg * 16);
        uint4 a = src[0], b = src[1];
        __half* gd = Hout + (size_t)m * 1024 + (n0 >> 2) + seg * 16;
        ((uint4*)gd)[0] = a; ((uint4*)gd)[1] = b;
    }
}

// ---------------- classifier tile (device fn) -------------------------------
__device__ __forceinline__ void cls_tile(
    __half* sm, const __half* __restrict__ hn, const __half* __restrict__ wc,
    const float* __restrict__ bc, float* __restrict__ out,
    int m0, int n0, int tid, int wm, int wn, int g, int tig)
{
    float* biasS = (float*)(sm + MAIN_H);
    if (tid < 128) {
        int np = n0 + tid;
        biasS[tid] = (np < C_) ? bc[np] : 0.f;
    }
    float acc[4][4][4];
#pragma unroll
    for (int a = 0; a < 4; a++)
#pragma unroll
        for (int b = 0; b < 4; b++)
#pragma unroll
            for (int c = 0; c < 4; c++) acc[a][b][c] = 0.f;

    run_mainloop<1>(sm, hn, wc, m0, n0, C_, acc, tid, wm, wn, g, tig);

#pragma unroll
    for (int mi = 0; mi < 4; mi++) {
        const int R0 = m0 + wm * 64 + mi * 16;
#pragma unroll
        for (int ni = 0; ni < 4; ni++) {
            const int v = n0 + wn * 32 + ni * 8 + 2 * tig;
            const float bA0 = biasS[v - n0], bA1 = biasS[v - n0 + 1];
            const int r1 = R0 + g, r2 = R0 + g + 8;
            int or1 = (r1 & 255) * S_ + (r1 >> 8);
            int or2 = (r2 & 255) * S_ + (r2 >> 8);
            if (v < C_) {
                out[(size_t)or1 * C_ + v] = acc[mi][ni][0] + bA0;
                out[(size_t)or2 * C_ + v] = acc[mi][ni][2] + bA0;
            }
            if (v + 1 < C_) {
                out[(size_t)or1 * C_ + v + 1] = acc[mi][ni][1] + bA1;
                out[(size_t)or2 * C_ + v + 1] = acc[mi][ni][3] + bA1;
            }
        }
    }
}

// ---------------- fused unroll LSTM step + cls piggyback -------------------
__global__ void __launch_bounds__(256, 2) k_mma_lstm(
    const __half* __restrict__ Hin, const __half* __restrict__ Whh,
    const float* __restrict__ xg,
    const float* __restrict__ Cin, float* __restrict__ Cout,
    __half* __restrict__ Hout, __half* __restrict__ hn, int final_t,
    int nact2, int t_cls,
    const __half* __restrict__ wc, const float* __restrict__ bc,
    float* __restrict__ out)
{
    extern __shared__ __half sm[];
    __half* hsm = sm + MAIN_H;
    const int tid = threadIdx.x, lane = tid & 31, wid = tid >> 5;
    const int wm = wid & 1, wn = wid >> 1, g = lane >> 2, tig = lane & 3;

    if ((int)blockIdx.y >= nact2) {
        if (blockIdx.x >= CLS_NB) return;
        int mb = t_cls * 2 + ((int)blockIdx.y - nact2);
        cls_tile(sm, hn, wc, bc, out, mb * 128, blockIdx.x * 128,
                 tid, wm, wn, g, tig);
        return;
    }

    const int m0 = blockIdx.y * 128, n0 = blockIdx.x * 128;

    float acc[4][4][4];
#pragma unroll
    for (int a = 0; a < 4; a++)
#pragma unroll
        for (int b = 0; b < 4; b++)
#pragma unroll
            for (int c = 0; c < 4; c++) acc[a][b][c] = 0.f;

    run_mainloop<0>(sm, Hin, Whh, m0, n0, 0x7fffffff, acc, tid, wm, wn, g, tig);

#pragma unroll
    for (int mi = 0; mi < 4; mi++) {
        const int R0 = m0 + wm * 64 + mi * 16;
#pragma unroll
        for (int ni = 0; ni < 4; ni++) {
            const int V0 = n0 + wn * 32 + ni * 8;
            float c0 = acc[mi][ni][0], c1 = acc[mi][ni][1];
            float c2 = acc[mi][ni][2], c3 = acc[mi][ni][3];
            int p = tig & 1;
            float x = p ? c0 : c2, y = p ? c1 : c3;
            float sx = __shfl_xor_sync(0xffffffffu, x, 1);
            float sy = __shfl_xor_sync(0xffffffffu, y, 1);
            float pi, pf, pg, po; int row;
            if (!p) { pi = c0; pf = c1; pg = sx; po = sy; row = R0 + g; }
            else    { pi = sx; pf = sy; pg = c2; po = c3; row = R0 + g + 8; }
            int u = (V0 >> 2) + (tig >> 1);
            float4 xv = *(const float4*)(xg + (size_t)row * G4 + u * 4);
            float ci = Cin[(size_t)row * 1024 + u];
            float cn = sigf(pf + xv.y) * ci + sigf(pi + xv.x) * tanhf(pg + xv.z);
            float hv = sigf(po + xv.w) * tanhf(cn);
            Cout[(size_t)row * 1024 + u] = cn;
            int ul = u - (n0 >> 2);
            hsm[(row - m0) * 32 + inv_l(ul)] = __float2half_rn(hv);
        }
    }
    __syncthreads();
    {
        int r = tid >> 1, seg = tid & 1;
        int m = m0 + r;
        const uint4* src = (const uint4*)(hsm + r * 32 + seg * 16);
        uint4 a = src[0], b = src[1];
        __half* gd = Hout + (size_t)m * 1024 + (n0 >> 2) + seg * 16;
        ((uint4*)gd)[0] = a; ((uint4*)gd)[1] = b;
        if ((m >> 8) == final_t) {
            __half* fd = hn + (size_t)m * 1024 + (n0 >> 2) + seg * 16;
            ((uint4*)fd)[0] = a; ((uint4*)fd)[1] = b;
        }
    }
}

// ---------------- standalone classifier chunk (instance t) -----------------
__global__ void __launch_bounds__(256, 2) k_cls(
    const __half* __restrict__ hn, const __half* __restrict__ wc,
    const float* __restrict__ bc, float* __restrict__ out, int t)
{
    extern __shared__ __half sm[];
    const int tid = threadIdx.x, lane = tid & 31, wid = tid >> 5;
    const int wm = wid & 1, wn = wid >> 1, g = lane >> 2, tig = lane & 3;
    int mb = t * 2 + blockIdx.y;
    cls_tile(sm, hn, wc, bc, out, mb * 128, blockIdx.x * 128, tid, wm, wn, g, tig);
}

// ---------------- merged prep kernel (fp32 -> fp16 + k-permute) ------------
#define PREP_XT   (SB * 32)
#define PREP_W    (G4 * 32)
#define PREP_WC   (C_ * 32)
#define PREP_TOT  (PREP_XT + 4 * PREP_W + PREP_WC)

__global__ void k_prep_all(
    const float* __restrict__ inp,
    const float* __restrict__ Whh_r, const float* __restrict__ Wih_r,
    const float* __restrict__ Wih_u, const float* __restrict__ Whh_u,
    const float* __restrict__ Wc,
    __half* __restrict__ xT, __half* __restrict__ whhr, __half* __restrict__ wihr,
    __half* __restrict__ wihu, __half* __restrict__ whhu, __half* __restrict__ wc)
{
    int idx = blockIdx.x * blockDim.x + threadIdx.x;
    if (idx >= PREP_TOT) return;
    const float* src;
    __half* dstbase;
    int r, b32;
    if (idx < PREP_XT) {
        r = idx >> 5; b32 = idx & 31;
        int b = r % B_, s = r / B_;
        src = inp + (size_t)(b * S_ + s) * 1024 + b32 * 32;
        dstbase = xT;
    } else {
        int t = idx - PREP_XT;
        int seg = t / PREP_W;
        if (seg < 4) {
            int u = t - seg * PREP_W;
            r = u >> 5; b32 = u & 31;
            int wr = ((r & 3) << 10) | (r >> 2);
            const float* W = (seg == 0) ? Whh_r : (seg == 1) ? Wih_r
                            : (seg == 2) ? Wih_u : Whh_u;
            src = W + (size_t)wr * 1024 + b32 * 32;
            dstbase = (seg == 0) ? whhr : (seg == 1) ? wihr
                    : (seg == 2) ? wihu : whhu;
        } else {
            int u = t - 4 * PREP_W;
            r = u >> 5; b32 = u & 31;
            src = Wc + (size_t)r * 1024 + b32 * 32;
            dstbase = wc;
        }
    }
    float v[32];
#pragma unroll
    for (int i = 0; i < 8; i++) *(float4*)&v[i * 4] = *(const float4*)(src + i * 4);
    __half h[32];
#pragma unroll
    for (int p = 0; p < 32; p++) h[p] = __float2half_rn(v[perm_l(p)]);
    uint4* dst = (uint4*)(dstbase + (size_t)r * 1024 + b32 * 32);
#pragma unroll
    for (int i = 0; i < 4; i++) dst[i] = ((const uint4*)h)[i];
}

// ---------------- host orchestration ----------------
extern "C" void kernel_launch(void* const* d_in, const int* in_sizes, int n_in,
                              void* d_out, int out_size) {
    (void)in_sizes; (void)n_in; (void)out_size;
    const float* inp   = (const float*)d_in[0];
    const float* Wih_r = (const float*)d_in[1];
    const float* Whh_r = (const float*)d_in[2];
    const float* bih_r = (const float*)d_in[3];
    const float* bhh_r = (const float*)d_in[4];
    const float* Wih_u = (const float*)d_in[5];
    const float* Whh_u = (const float*)d_in[6];
    const float* bih_u = (const float*)d_in[7];
    const float* bhh_u = (const float*)d_in[8];
    const float* Wc    = (const float*)d_in[9];
    const float* bc    = (const float*)d_in[10];
    float* out = (float*)d_out;

    __half *xT, *hu, *hn, *whhr, *wihr, *wihu, *whhu, *wc;
    float *xg_r, *xg_u, *cu;
    cudaGetSymbolAddress((void**)&xT,   g_xT);
    cudaGetSymbolAddress((void**)&xg_r, g_xg_r);
    cudaGetSymbolAddress((void**)&xg_u, g_xg_u);
    cudaGetSymbolAddress((void**)&hu,   g_hu);
    cudaGetSymbolAddress((void**)&cu,   g_cu);
    cudaGetSymbolAddress((void**)&hn,   g_hn);
    cudaGetSymbolAddress((void**)&whhr, g_whhr);
    cudaGetSymbolAddress((void**)&wihr, g_wihr);
    cudaGetSymbolAddress((void**)&wihu, g_wihu);
    cudaGetSymbolAddress((void**)&whhu, g_whhu);
    cudaGetSymbolAddress((void**)&wc,   g_wc);
    __half* hu0 = hu;
    __half* hu1 = hu + (size_t)SB * 1024;

    cudaFuncSetAttribute(k_mma_lstm, cudaFuncAttributeMaxDynamicSharedMemorySize, SMEM_LSTM);
    cudaFuncSetAttribute(k_roll,     cudaFuncAttributeMaxDynamicSharedMemorySize, SMEM_LSTM);
    cudaFuncSetAttribute(k_projq,    cudaFuncAttributeMaxDynamicSharedMemorySize, SMEM_LIN);
    cudaFuncSetAttribute(k_cls,      cudaFuncAttributeMaxDynamicSharedMemorySize, SMEM_LIN);

    // 0) prep: all operands -> fp16 (+permute)
    k_prep_all<<<(PREP_TOT + 255) / 256, 256>>>(inp, Whh_r, Wih_r, Wih_u, Whh_u, Wc,
                                                xT, whhr, wihr, wihu, whhu, wc);

    // 1) proj pre-launch: first 608 queue tiles (xg_r slices 0..8 + start of rest)
    k_projq<<<PRELAUNCH, 256, SMEM_LIN>>>(xT, wihr, wihu, xg_r, xg_u,
                                          bih_r, bhh_r, bih_u, bhh_u);

    // 2) rolling LSTM: 14 steps, each 64 LSTM tiles + 88 proj riders
    //    (152 CTAs = one per SM; riders never share an SM with a rolling tile)
    for (int t = 0; t < S_; t++) {
        const __half* hin = hu0 + (size_t)(t - 1) * BH;   // unused when t==0
        const float*  cin = cu + (size_t)(t - 1) * BH;
        k_roll<<<64 + RIDE, 256, SMEM_LSTM>>>(
            (t == 0) ? hu0 : hin, whhr,
            xg_r + (size_t)t * B_ * G4,
            (t == 0) ? cu : cin, cu + (size_t)t * BH,
            hu0 + (size_t)t * BH,
            (t == 0) ? 1 : 0, PRELAUNCH + RIDE * t,
            xT, wihr, wihu, xg_r, xg_u, bih_r, bhh_r, bih_u, bhh_u);
    }

    // 3) unroll LSTM: 15 steps; steps j>=2 carry classifier chunk for t=15-j
    for (int j = 0; j <= S_; j++) {
        int nact = (15 - j < 14) ? (15 - j) : 14;
        const __half* hin = (j & 1) ? hu1 : hu0;
        __half*       ho  = (j & 1) ? hu0 : hu1;
        int final_t = S_ - j;
        int t_cls = (j >= 2) ? (15 - j) : -1;
        dim3 g(G4 / 128, nact * 2 + ((t_cls >= 0) ? 2 : 0));
        k_mma_lstm<<<g, 256, SMEM_LSTM>>>(hin, whhu, xg_u, cu, cu, ho, hn,
                                          final_t, nact * 2, t_cls,
                                          wc, bc, out);
    }

    // 4) final classifier chunk (instance t=0)
    {
        dim3 g(CLS_NB, 2);
        k_cls<<<g, 256, SMEM_LIN>>>(hn, wc, bc, out, 0);
    }
}